// round 13
// baseline (speedup 1.0000x reference)
#include <cuda_runtime.h>
#include <cuda_fp16.h>
#include <math.h>
#include <stdint.h>

#define BB 2
#define TT 8192
#define CC 1024
#define HH 16
#define DD 64
#define MTOT (BB*TT)        // 16384
#define QKVC (3*CC)         // 3072

// ---------------- device scratch ----------------
__device__ __half g_qkv[(size_t)MTOT * QKVC];      // 96 MB fp16
__device__ __half g_xh[(size_t)MTOT * CC];
__device__ __half g_sh[(size_t)MTOT * CC];
__device__ __half g_wqh[(size_t)QKVC * CC];
__device__ __half g_woh[(size_t)CC * CC];
__device__ float g_cos[TT * 32];
__device__ float g_sin[TT * 32];

// ---------------- PTX helpers ----------------
__device__ __forceinline__ uint32_t smem_u32(const void* p) {
    uint32_t a;
    asm("{ .reg .u64 t; cvta.to.shared.u64 t, %1; cvt.u32.u64 %0, t; }" : "=r"(a) : "l"(p));
    return a;
}
__device__ __forceinline__ void cp16(uint32_t s, const void* g) {
    asm volatile("cp.async.cg.shared.global [%0], [%1], 16;" :: "r"(s), "l"(g));
}
#define CP_COMMIT() asm volatile("cp.async.commit_group;" ::: "memory")
#define CP_WAIT(n)  asm volatile("cp.async.wait_group %0;" :: "n"(n) : "memory")

__device__ __forceinline__ void ldsm_x4(uint32_t* r, uint32_t addr) {
    asm volatile("ldmatrix.sync.aligned.m8n8.x4.shared.b16 {%0,%1,%2,%3}, [%4];"
                 : "=r"(r[0]), "=r"(r[1]), "=r"(r[2]), "=r"(r[3]) : "r"(addr));
}
#define MMA_F16(d, a, b0, b1) \
    asm volatile("mma.sync.aligned.m16n8k16.row.col.f32.f16.f16.f32 " \
                 "{%0,%1,%2,%3}, {%4,%5,%6,%7}, {%8,%9}, {%0,%1,%2,%3};" \
                 : "+f"((d)[0]), "+f"((d)[1]), "+f"((d)[2]), "+f"((d)[3]) \
                 : "r"((a)[0]), "r"((a)[1]), "r"((a)[2]), "r"((a)[3]), \
                   "r"(b0), "r"(b1))

// ---------------- small kernels ----------------
__global__ void rope_table_kernel() {
    int idx = blockIdx.x * blockDim.x + threadIdx.x;
    if (idx >= TT * 32) return;
    int t = idx >> 5, d2 = idx & 31;
    float invf = (float)pow(10000.0, -(double)d2 / 32.0);
    float ang = __fmul_rn((float)t, invf);
    g_cos[idx] = (float)cos((double)ang);
    g_sin[idx] = (float)sin((double)ang);
}

__global__ void cvt_kernel(const float4* __restrict__ in,
                           __half2* __restrict__ hi, int n4) {
    int base = blockIdx.x * 1024 + threadIdx.x;
    float4 v[4];
#pragma unroll
    for (int k = 0; k < 4; ++k) v[k] = in[base + k * 256];
#pragma unroll
    for (int k = 0; k < 4; ++k) {
        int f = base + k * 256;
        __half2 a = __floats2half2_rn(v[k].x, v[k].y);
        __half2 b = __floats2half2_rn(v[k].z, v[k].w);
        uint2 pk; pk.x = *(uint32_t*)&a; pk.y = *(uint32_t*)&b;
        ((uint2*)hi)[f] = pk;
    }
}

// ---------------- persistent fp16 GEMM (NT), 2 CTAs/SM ----------------
// CTA tile 128x128, 4 warps (2x2 of 64x64 warp tiles), BK=64, 3-stage ring.
// 2 CTAs per SM: cross-CTA interleave hides barrier/wait/epilogue stalls.
#define BM 128
#define BN 128
#define BKQ 64
#define KITER 16            // K(=1024)/BKQ
#define T_A 0
#define T_B (16*1024)
#define STG  (32*1024)
#define NSTAGE 3
#define GEMM_DYN (NSTAGE*STG + 1024)

extern __shared__ char dynsmem[];

template <typename OutT>
__global__ __launch_bounds__(128, 2) void gemm_mma(
    const __half* __restrict__ Ah,
    const __half* __restrict__ Bh,
    OutT* __restrict__ C, int ldc, int K, int ntN, int ntiles)
{
    const int tid  = threadIdx.x;
    const int wid  = tid >> 5;
    const int lane = tid & 31;
    const int wm = (wid >> 1) * 64;
    const int wn = (wid & 1) * 64;
    const int bx = blockIdx.x;
    const int grid = gridDim.x;

    const int my_nt = bx < ntiles ? (ntiles - 1 - bx) / grid + 1 : 0;
    const int my_iters = my_nt * KITER;

    uint32_t sbase = (smem_u32(dynsmem) + 1023u) & ~1023u;

    // ---- loader: each thread owns one 128B row of A and one of B (8 cp16 each)
    const int lrow = tid;          // 0..127
    uint32_t soff[8];
#pragma unroll
    for (int c = 0; c < 8; ++c) {
        uint32_t off = (uint32_t)lrow * 128 + (uint32_t)c * 16;
        soff[c] = off ^ ((off >> 3) & 0x70);
    }

    int ld_tile = bx;
    int ld_tm = ld_tile / ntN;
    int ld_tn = ld_tile - ld_tm * ntN;
    int ld_kk = 0;
    int ld_stage = 0;

    auto load_stage = [&]() {
        const __half* gA = Ah + (size_t)(ld_tm * BM + lrow) * K + ld_kk * BKQ;
        const __half* gB = Bh + (size_t)(ld_tn * BN + lrow) * K + ld_kk * BKQ;
        uint32_t st = sbase + (uint32_t)ld_stage * STG;
#pragma unroll
        for (int c = 0; c < 8; ++c) {
            cp16(st + T_A + soff[c], gA + c * 8);
            cp16(st + T_B + soff[c], gB + c * 8);
        }
        CP_COMMIT();
        if (++ld_stage == NSTAGE) ld_stage = 0;
        if (++ld_kk == KITER) {
            ld_kk = 0;
            ld_tile += grid;
            ld_tm = ld_tile / ntN;
            ld_tn = ld_tile - ld_tm * ntN;
        }
    };

    // ---- ldmatrix address precompute (tile-invariant) ----
    uint32_t a_rt[4], a_xr[4];
#pragma unroll
    for (int ti = 0; ti < 4; ++ti) {
        int r = wm + ti * 16 + (lane & 15);
        a_rt[ti] = (uint32_t)r * 128;
        a_xr[ti] = (uint32_t)(r & 7) << 4;
    }
    const uint32_t a_cb = (uint32_t)(lane >> 4) * 16;
    uint32_t b_rt[4], b_xr[4];
#pragma unroll
    for (int ni = 0; ni < 4; ++ni) {
        int r = wn + ni * 16 + (lane & 7) + (lane >> 4) * 8;
        b_rt[ni] = (uint32_t)r * 128;
        b_xr[ni] = (uint32_t)(r & 7) << 4;
    }
    const uint32_t b_cb = (uint32_t)((lane >> 3) & 1) * 16;

    float acc[4][8][4];
#pragma unroll
    for (int i = 0; i < 4; ++i)
#pragma unroll
        for (int j = 0; j < 8; ++j)
#pragma unroll
            for (int q = 0; q < 4; ++q) acc[i][j][q] = 0.f;

    if (my_iters == 0) return;

    // ---- prologue: 2 stages in flight ----
    load_stage();
    if (1 < my_iters) load_stage();

    // ---- mainloop ----
    int rd_stage = 0;
    for (int ci = 0; ci < my_iters; ++ci) {
        if (ci + 2 < my_iters) {
            CP_WAIT(1);
            __syncthreads();
            load_stage();
        } else {
            CP_WAIT(0);
            __syncthreads();
        }

        uint32_t base = sbase + (uint32_t)rd_stage * STG;
        if (++rd_stage == NSTAGE) rd_stage = 0;

#pragma unroll
        for (int ks = 0; ks < 4; ++ks) {
            const uint32_t kb = (uint32_t)ks * 32;
            uint32_t ah[4][4], bh[4][4];
#pragma unroll
            for (int ni = 0; ni < 4; ++ni)
                ldsm_x4(bh[ni], base + T_B + b_rt[ni] + ((b_cb + kb) ^ b_xr[ni]));
#pragma unroll
            for (int ti = 0; ti < 4; ++ti)
                ldsm_x4(ah[ti], base + T_A + a_rt[ti] + ((a_cb + kb) ^ a_xr[ti]));

#pragma unroll
            for (int mi = 0; mi < 4; ++mi)
#pragma unroll
                for (int ni = 0; ni < 4; ++ni) {
                    MMA_F16(acc[mi][2*ni],   ah[mi], bh[ni][0], bh[ni][1]);
                    MMA_F16(acc[mi][2*ni+1], ah[mi], bh[ni][2], bh[ni][3]);
                }
        }

        // ---- tile finished: epilogue ----
        if ((ci & (KITER - 1)) == KITER - 1) {
            int tile = bx + (ci >> 4) * grid;
            int tm = tile / ntN;
            int tn = tile - tm * ntN;
#pragma unroll
            for (int mi = 0; mi < 4; ++mi) {
                int gm = tm * BM + wm + mi * 16 + (lane >> 2);
#pragma unroll
                for (int ni = 0; ni < 8; ++ni) {
                    int gn = tn * BN + wn + ni * 8 + (lane & 3) * 2;
                    if constexpr (sizeof(OutT) == 4) {
                        float2 v0 = make_float2(acc[mi][ni][0], acc[mi][ni][1]);
                        float2 v1 = make_float2(acc[mi][ni][2], acc[mi][ni][3]);
                        *(float2*)((float*)C + (size_t)gm * ldc + gn) = v0;
                        *(float2*)((float*)C + (size_t)(gm + 8) * ldc + gn) = v1;
                    } else {
                        __half2 h0; h0.x = __float2half_rn(acc[mi][ni][0]); h0.y = __float2half_rn(acc[mi][ni][1]);
                        __half2 h1; h1.x = __float2half_rn(acc[mi][ni][2]); h1.y = __float2half_rn(acc[mi][ni][3]);
                        *(__half2*)((__half*)C + (size_t)gm * ldc + gn) = h0;
                        *(__half2*)((__half*)C + (size_t)(gm + 8) * ldc + gn) = h1;
                    }
                }
            }
#pragma unroll
            for (int i = 0; i < 4; ++i)
#pragma unroll
                for (int j = 0; j < 8; ++j)
#pragma unroll
                    for (int q = 0; q < 4; ++q) acc[i][j][q] = 0.f;
        }
    }
}

// ---------------- fused RoPE + 16x16 head-attn, 2 tokens per block ----------------
#define PAD 65
__global__ __launch_bounds__(256) void attn_kernel()
{
    __shared__ float q [2][HH][PAD];
    __shared__ float kk[2][HH][PAD];
    __shared__ float vv[2][HH][PAD];
    __shared__ float sc[2][HH][17];
    __shared__ float cs[2][32], sn[2][32];

    const int tok0 = blockIdx.x * 2;
    const int tid = threadIdx.x;

    if (tid < 64) {
        int tk = tid >> 5, d2 = tid & 31;
        int t = (tok0 + tk) & (TT - 1);
        cs[tk][d2] = g_cos[t*32 + d2];
        sn[tk][d2] = g_sin[t*32 + d2];
    }

    const float4* base = (const float4*)(g_qkv + (size_t)tok0 * QKVC);
#pragma unroll
    for (int r = 0; r < 3; ++r) {
        int id = r * 256 + tid;
        float4 raw = base[id];
        int tk = id >= 384;
        int f  = id - tk * 384;
        int s  = f >> 7;
        int h  = (f >> 3) & 15;
        int d0 = (f & 7) * 8;
        float* dst = (s == 0 ? &q[tk][h][d0] : s == 1 ? &kk[tk][h][d0] : &vv[tk][h][d0]);
        const __half2* hp = (const __half2*)&raw;
#pragma unroll
        for (int j = 0; j < 4; ++j) {
            float2 fv = __half22float2(hp[j]);
            dst[2*j]   = fv.x;
            dst[2*j+1] = fv.y;
        }
    }
    __syncthreads();

#pragma unroll
    for (int r = 0; r < 8; ++r) {
        int idx = tid + 256 * r;
        int tk = idx >> 10;
        int which = (idx >> 9) & 1;
        int h = (idx >> 5) & 15;
        int d2 = idx & 31;
        float c = cs[tk][d2], s = sn[tk][d2];
        float* buf = which ? &kk[tk][0][0] : &q[tk][0][0];
        float x1 = buf[h*PAD + 2*d2];
        float x2 = buf[h*PAD + 2*d2 + 1];
        buf[h*PAD + 2*d2]     = x1*c - x2*s;
        buf[h*PAD + 2*d2 + 1] = x2*c + x1*s;
    }
    __syncthreads();

#pragma unroll
    for (int r = 0; r < 2; ++r) {
        int idx = tid + 256 * r;
        int tk = idx >> 8;
        int hq = (idx >> 4) & 15, hk = idx & 15;
        float s = 0.f;
#pragma unroll
        for (int d = 0; d < DD; ++d) s = fmaf(q[tk][hq][d], kk[tk][hk][d], s);
        sc[tk][hq][hk] = s * 0.125f;
    }
    __syncthreads();

    if (tid < 32) {
        int tk = tid >> 4, row = tid & 15;
        float mx = -1e30f;
#pragma unroll
        for (int j = 0; j < 16; ++j) mx = fmaxf(mx, sc[tk][row][j]);
        float sum = 0.f;
#pragma unroll
        for (int j = 0; j < 16; ++j) { float e = expf(sc[tk][row][j] - mx); sc[tk][row][j] = e; sum += e; }
        float inv = 1.f / sum;
#pragma unroll
        for (int j = 0; j < 16; ++j) sc[tk][row][j] *= inv;
    }
    __syncthreads();

#pragma unroll
    for (int r = 0; r < 8; ++r) {
        int idx = tid + 256 * r;
        int tk = idx >> 10;
        int hq = (idx >> 6) & 15, d = idx & 63;
        float o = 0.f;
#pragma unroll
        for (int hk = 0; hk < 16; ++hk) o = fmaf(sc[tk][hq][hk], vv[tk][hk][d], o);
        int tg = tok0 + tk;
        int b = tg >> 13, t = tg & (TT - 1);
        size_t obase = ((size_t)b * TT + (t >> 4)) * (size_t)CC + (size_t)(t & 15) * DD;
        g_sh[obase + (size_t)hq * 512 * CC + d] = __float2half_rn(o);
    }
}

// ---------------------------------------------------------------------------
extern "C" void kernel_launch(void* const* d_in, const int* in_sizes, int n_in,
                              void* d_out, int out_size)
{
    const float* x    = (const float*)d_in[0];
    const float* Wqkv = (const float*)d_in[1];
    const float* Wout = (const float*)d_in[2];
    float* out = (float*)d_out;

    __half *qkv_p, *xh, *sh, *wqh, *woh;
    cudaGetSymbolAddress((void**)&qkv_p, g_qkv);
    cudaGetSymbolAddress((void**)&xh, g_xh);
    cudaGetSymbolAddress((void**)&sh, g_sh);
    cudaGetSymbolAddress((void**)&wqh, g_wqh);
    cudaGetSymbolAddress((void**)&woh, g_woh);

    int nsm = 148;
    cudaDeviceGetAttribute(&nsm, cudaDevAttrMultiProcessorCount, 0);

    cudaFuncSetAttribute(gemm_mma<__half>, cudaFuncAttributeMaxDynamicSharedMemorySize, GEMM_DYN);
    cudaFuncSetAttribute(gemm_mma<float>,  cudaFuncAttributeMaxDynamicSharedMemorySize, GEMM_DYN);

    rope_table_kernel<<<(TT*32 + 255) / 256, 256>>>();
    cvt_kernel<<<(MTOT*CC/4) / 1024, 256>>>((const float4*)x,    (__half2*)xh,  MTOT*CC/4);
    cvt_kernel<<<(QKVC*CC/4) / 1024, 256>>>((const float4*)Wqkv, (__half2*)wqh, QKVC*CC/4);
    cvt_kernel<<<(CC*CC/4)   / 1024, 256>>>((const float4*)Wout, (__half2*)woh, CC*CC/4);

    // GEMM1: qkv(fp16) = x @ Wqkv^T  (M=16384, N=3072, K=1024) — 3072 tiles
    {
        int ntiles = (QKVC / BN) * (MTOT / BM);
        int grid = ntiles < 2 * nsm ? ntiles : 2 * nsm;
        gemm_mma<__half><<<grid, 128, GEMM_DYN>>>(xh, wqh, qkv_p, QKVC, CC, QKVC / BN, ntiles);
    }

    // fused RoPE + head-attention + scramble (2 tokens/block)
    attn_kernel<<<MTOT / 2, 256>>>();

    // GEMM2: out = scr @ Wout^T (M=16384, N=1024, K=1024) — 1024 tiles
    {
        int ntiles = (CC / BN) * (MTOT / BM);
        int grid = ntiles < 2 * nsm ? ntiles : 2 * nsm;
        gemm_mma<float><<<grid, 128, GEMM_DYN>>>(sh, woh, out, CC, CC, CC / BN, ntiles);
    }
}

// round 14
// speedup vs baseline: 1.2729x; 1.2729x over previous
#include <cuda_runtime.h>
#include <cuda_fp16.h>
#include <math.h>
#include <stdint.h>

#define BB 2
#define TT 8192
#define CC 1024
#define HH 16
#define DD 64
#define MTOT (BB*TT)        // 16384
#define QKVC (3*CC)         // 3072

// ---------------- device scratch ----------------
__device__ __half g_qkv[(size_t)MTOT * QKVC];      // 96 MB fp16
__device__ __half g_xh[(size_t)MTOT * CC];
__device__ __half g_sh[(size_t)MTOT * CC];
__device__ __half g_wqh[(size_t)QKVC * CC];
__device__ __half g_woh[(size_t)CC * CC];
__device__ float g_cos[TT * 32];
__device__ float g_sin[TT * 32];

// ---------------- PTX helpers ----------------
__device__ __forceinline__ uint32_t smem_u32(const void* p) {
    uint32_t a;
    asm("{ .reg .u64 t; cvta.to.shared.u64 t, %1; cvt.u32.u64 %0, t; }" : "=r"(a) : "l"(p));
    return a;
}
__device__ __forceinline__ void cp16(uint32_t s, const void* g) {
    asm volatile("cp.async.cg.shared.global [%0], [%1], 16;" :: "r"(s), "l"(g));
}
#define CP_COMMIT() asm volatile("cp.async.commit_group;" ::: "memory")
#define CP_WAIT(n)  asm volatile("cp.async.wait_group %0;" :: "n"(n) : "memory")

__device__ __forceinline__ void ldsm_x4(uint32_t* r, uint32_t addr) {
    asm volatile("ldmatrix.sync.aligned.m8n8.x4.shared.b16 {%0,%1,%2,%3}, [%4];"
                 : "=r"(r[0]), "=r"(r[1]), "=r"(r[2]), "=r"(r[3]) : "r"(addr));
}
#define MMA_F16(d, a, b0, b1) \
    asm volatile("mma.sync.aligned.m16n8k16.row.col.f32.f16.f16.f32 " \
                 "{%0,%1,%2,%3}, {%4,%5,%6,%7}, {%8,%9}, {%0,%1,%2,%3};" \
                 : "+f"((d)[0]), "+f"((d)[1]), "+f"((d)[2]), "+f"((d)[3]) \
                 : "r"((a)[0]), "r"((a)[1]), "r"((a)[2]), "r"((a)[3]), \
                   "r"(b0), "r"(b1))

// ---------------- small kernels ----------------
__global__ void rope_table_kernel() {
    int idx = blockIdx.x * blockDim.x + threadIdx.x;
    if (idx >= TT * 32) return;
    int t = idx >> 5, d2 = idx & 31;
    float invf = (float)pow(10000.0, -(double)d2 / 32.0);
    float ang = __fmul_rn((float)t, invf);
    g_cos[idx] = (float)cos((double)ang);
    g_sin[idx] = (float)sin((double)ang);
}

// single merged fp32->fp16 convert for x, Wqkv, Wout.
// Block quantum = 1024 float4. Region sizes (in float4): x 4096*1024, wq 768*1024, wo 256*1024.
__global__ void cvt_all_kernel(const float4* __restrict__ x,
                               const float4* __restrict__ wq,
                               const float4* __restrict__ wo,
                               uint2* __restrict__ xh,
                               uint2* __restrict__ wqh,
                               uint2* __restrict__ woh) {
    int blk = blockIdx.x;
    const float4* in;
    uint2* out;
    int base;
    if (blk < 4096)      { in = x;  out = xh;  base = blk * 1024; }
    else if (blk < 4864) { in = wq; out = wqh; base = (blk - 4096) * 1024; }
    else                 { in = wo; out = woh; base = (blk - 4864) * 1024; }
    int idx = base + threadIdx.x;
    float4 v[4];
#pragma unroll
    for (int k = 0; k < 4; ++k) v[k] = in[idx + k * 256];
#pragma unroll
    for (int k = 0; k < 4; ++k) {
        __half2 a = __floats2half2_rn(v[k].x, v[k].y);
        __half2 b = __floats2half2_rn(v[k].z, v[k].w);
        uint2 pk; pk.x = *(uint32_t*)&a; pk.y = *(uint32_t*)&b;
        out[idx + k * 256] = pk;
    }
}

// ---------------- persistent fp16 GEMM (NT): C[m,n] = sum_k A[m,k]*B[n,k] ----------------
// (R12 configuration — best known) CTA tile 128x256, warp tile 64x64 (2x4 warps),
// BK=64, 4-stage cp.async ring, pair-window + fragment double-buffering.
#define BM 128
#define BN 256
#define BKQ 64
#define KITER 16            // K(=1024)/BKQ
#define T_A 0
#define T_B (16*1024)
#define STG  (48*1024)
#define NSTAGE 4
#define GEMM_DYN (NSTAGE*STG + 1024)

extern __shared__ char dynsmem[];

template <typename OutT>
__global__ __launch_bounds__(256, 1) void gemm_mma(
    const __half* __restrict__ Ah,
    const __half* __restrict__ Bh,
    OutT* __restrict__ C, int ldc, int K, int ntN, int ntiles)
{
    const int tid  = threadIdx.x;
    const int lane = tid & 31;
    const int wid  = tid >> 5;
    const int wm = (wid >> 2) * 64;
    const int wn = (wid & 3) * 64;
    const int bx = blockIdx.x;
    const int grid = gridDim.x;

    const int my_nt = (ntiles - 1 - bx) / grid + 1;
    const int my_iters = my_nt * KITER;       // always even

    uint32_t sbase = (smem_u32(dynsmem) + 1023u) & ~1023u;

    const int lrow = tid >> 1;
    const int lc4  = (tid & 1) * 4;
    uint32_t soffA[4], soffB1[4];
#pragma unroll
    for (int c = 0; c < 4; ++c) {
        uint32_t offA = (uint32_t)lrow * 128 + (uint32_t)(lc4 + c) * 16;
        soffA[c] = offA ^ ((offA >> 3) & 0x70);
        uint32_t offB1 = (uint32_t)(lrow + 128) * 128 + (uint32_t)(lc4 + c) * 16;
        soffB1[c] = offB1 ^ ((offB1 >> 3) & 0x70);
    }
    const int gcol = lc4 * 8;

    int ld_tile = bx;
    int ld_tm = ld_tile / ntN;
    int ld_tn = ld_tile - ld_tm * ntN;
    int ld_kk = 0;
    int ld_stage = 0;

    auto load_stage = [&]() {
        const __half* gA  = Ah + (size_t)(ld_tm * BM + lrow) * K + ld_kk * BKQ + gcol;
        const __half* gB0 = Bh + (size_t)(ld_tn * BN + lrow) * K + ld_kk * BKQ + gcol;
        const __half* gB1 = gB0 + (size_t)128 * K;
        uint32_t st = sbase + (uint32_t)(ld_stage & (NSTAGE - 1)) * STG;
#pragma unroll
        for (int c = 0; c < 4; ++c) {
            cp16(st + T_A + soffA[c],  gA  + c * 8);
            cp16(st + T_B + soffA[c],  gB0 + c * 8);
            cp16(st + T_B + soffB1[c], gB1 + c * 8);
        }
        CP_COMMIT();
        ++ld_stage;
        if (++ld_kk == KITER) {
            ld_kk = 0;
            ld_tile += grid;
            ld_tm = ld_tile / ntN;
            ld_tn = ld_tile - ld_tm * ntN;
        }
    };

    uint32_t a_rt[4], a_xr[4];
#pragma unroll
    for (int ti = 0; ti < 4; ++ti) {
        int r = wm + ti * 16 + (lane & 15);
        a_rt[ti] = (uint32_t)r * 128;
        a_xr[ti] = (uint32_t)(r & 7) << 4;
    }
    const uint32_t a_cb = (uint32_t)(lane >> 4) * 16;
    uint32_t b_rt[4], b_xr[4];
#pragma unroll
    for (int ni = 0; ni < 4; ++ni) {
        int r = wn + ni * 16 + (lane & 7) + (lane >> 4) * 8;
        b_rt[ni] = (uint32_t)r * 128;
        b_xr[ni] = (uint32_t)(r & 7) << 4;
    }
    const uint32_t b_cb = (uint32_t)((lane >> 3) & 1) * 16;

    float acc[4][8][4];
#pragma unroll
    for (int i = 0; i < 4; ++i)
#pragma unroll
        for (int j = 0; j < 8; ++j)
#pragma unroll
            for (int q = 0; q < 4; ++q) acc[i][j][q] = 0.f;

    load_stage();
    load_stage();

    for (int cp = 0; cp < my_iters; cp += 2) {
        CP_WAIT(0);
        __syncthreads();
        if (cp + 2 < my_iters) load_stage();
        if (cp + 3 < my_iters) load_stage();

        const uint32_t base0 = sbase + (uint32_t)((cp)     & (NSTAGE - 1)) * STG;
        const uint32_t base1 = sbase + (uint32_t)((cp + 1) & (NSTAGE - 1)) * STG;

        uint32_t ah[2][4][4], bh[2][4][4];
#pragma unroll
        for (int ni = 0; ni < 4; ++ni)
            ldsm_x4(bh[0][ni], base0 + T_B + b_rt[ni] + (b_cb ^ b_xr[ni]));
#pragma unroll
        for (int ti = 0; ti < 4; ++ti)
            ldsm_x4(ah[0][ti], base0 + T_A + a_rt[ti] + (a_cb ^ a_xr[ti]));

#pragma unroll
        for (int s = 0; s < 8; ++s) {
            const int cur = s & 1;
            const int nx  = cur ^ 1;
            if (s < 7) {
                const uint32_t bb = (s + 1 < 4) ? base0 : base1;
                const uint32_t kb = (uint32_t)((s + 1) & 3) * 32;
#pragma unroll
                for (int ni = 0; ni < 4; ++ni)
                    ldsm_x4(bh[nx][ni], bb + T_B + b_rt[ni] + ((b_cb + kb) ^ b_xr[ni]));
#pragma unroll
                for (int ti = 0; ti < 4; ++ti)
                    ldsm_x4(ah[nx][ti], bb + T_A + a_rt[ti] + ((a_cb + kb) ^ a_xr[ti]));
            }
#pragma unroll
            for (int mi = 0; mi < 4; ++mi)
#pragma unroll
                for (int ni = 0; ni < 4; ++ni) {
                    MMA_F16(acc[mi][2*ni],   ah[cur][mi], bh[cur][ni][0], bh[cur][ni][1]);
                    MMA_F16(acc[mi][2*ni+1], ah[cur][mi], bh[cur][ni][2], bh[cur][ni][3]);
                }
        }

        if (((cp + 1) & (KITER - 1)) == KITER - 1) {
            int tile = bx + ((cp + 1) >> 4) * grid;
            int tm = tile / ntN;
            int tn = tile - tm * ntN;
#pragma unroll
            for (int mi = 0; mi < 4; ++mi) {
                int gm = tm * BM + wm + mi * 16 + (lane >> 2);
#pragma unroll
                for (int ni = 0; ni < 8; ++ni) {
                    int gn = tn * BN + wn + ni * 8 + (lane & 3) * 2;
                    if constexpr (sizeof(OutT) == 4) {
                        float2 v0 = make_float2(acc[mi][ni][0], acc[mi][ni][1]);
                        float2 v1 = make_float2(acc[mi][ni][2], acc[mi][ni][3]);
                        *(float2*)((float*)C + (size_t)gm * ldc + gn) = v0;
                        *(float2*)((float*)C + (size_t)(gm + 8) * ldc + gn) = v1;
                    } else {
                        __half2 h0; h0.x = __float2half_rn(acc[mi][ni][0]); h0.y = __float2half_rn(acc[mi][ni][1]);
                        __half2 h1; h1.x = __float2half_rn(acc[mi][ni][2]); h1.y = __float2half_rn(acc[mi][ni][3]);
                        *(__half2*)((__half*)C + (size_t)gm * ldc + gn) = h0;
                        *(__half2*)((__half*)C + (size_t)(gm + 8) * ldc + gn) = h1;
                    }
                }
            }
#pragma unroll
            for (int i = 0; i < 4; ++i)
#pragma unroll
                for (int j = 0; j < 8; ++j)
#pragma unroll
                    for (int q = 0; q < 4; ++q) acc[i][j][q] = 0.f;
        }
    }
}

// ---------------- fused RoPE + 16x16 head-attn, 4 tokens per block ----------------
// dynamic smem layout (floats): q[4][16][65] | k[..] | v[..] | sc[4][16][17] | cs[4][32] | sn[4][32]
#define PAD 65
#define AQ_OFF 0
#define AK_OFF 4160
#define AV_OFF 8320
#define ASC_OFF 12480
#define ACS_OFF 13568
#define ASN_OFF 13696
#define ATTN_DYN (13824 * 4)

__global__ __launch_bounds__(256) void attn_kernel()
{
    float* sm = (float*)dynsmem;
    float* q  = sm + AQ_OFF;
    float* kk = sm + AK_OFF;
    float* vv = sm + AV_OFF;
    float* sc = sm + ASC_OFF;
    float* cs = sm + ACS_OFF;
    float* sn = sm + ASN_OFF;

    const int tok0 = blockIdx.x * 4;
    const int tid = threadIdx.x;

    if (tid < 128) {
        int tk = tid >> 5, d2 = tid & 31;
        int t = (tok0 + tk) & (TT - 1);
        cs[tk*32 + d2] = g_cos[t*32 + d2];
        sn[tk*32 + d2] = g_sin[t*32 + d2];
    }

    // load 4 tokens x 3072 halfs = 1536 float4, 6 per thread
    const float4* base = (const float4*)(g_qkv + (size_t)tok0 * QKVC);
#pragma unroll
    for (int r = 0; r < 6; ++r) {
        int id = r * 256 + tid;          // 0..1535
        float4 raw = base[id];
        int tk = id / 384;
        int f  = id - tk * 384;          // 0..383
        int s  = f >> 7;                 // 0=q 1=k 2=v
        int h  = (f >> 3) & 15;
        int d0 = (f & 7) * 8;
        float* dst = (s == 0 ? q : s == 1 ? kk : vv) + (tk*16 + h) * PAD + d0;
        const __half2* hp = (const __half2*)&raw;
#pragma unroll
        for (int j = 0; j < 4; ++j) {
            float2 fv = __half22float2(hp[j]);
            dst[2*j]   = fv.x;
            dst[2*j+1] = fv.y;
        }
    }
    __syncthreads();

    // RoPE: 4 tokens x (q,k) x 16 heads x 32 pairs = 4096 -> 16 per thread
#pragma unroll
    for (int r = 0; r < 16; ++r) {
        int idx = tid + 256 * r;
        int tk = idx >> 10;
        int which = (idx >> 9) & 1;
        int h = (idx >> 5) & 15;
        int d2 = idx & 31;
        float c = cs[tk*32 + d2], s = sn[tk*32 + d2];
        float* buf = (which ? kk : q) + (tk*16 + h) * PAD;
        float x1 = buf[2*d2];
        float x2 = buf[2*d2 + 1];
        buf[2*d2]     = x1*c - x2*s;
        buf[2*d2 + 1] = x2*c + x1*s;
    }
    __syncthreads();

    // scores: 4 x 256 = 1024 -> 4 per thread
#pragma unroll
    for (int r = 0; r < 4; ++r) {
        int idx = tid + 256 * r;
        int tk = idx >> 8;
        int hq = (idx >> 4) & 15, hk = idx & 15;
        const float* qr = q  + (tk*16 + hq) * PAD;
        const float* kr = kk + (tk*16 + hk) * PAD;
        float s = 0.f;
#pragma unroll
        for (int d = 0; d < DD; ++d) s = fmaf(qr[d], kr[d], s);
        sc[(tk*16 + hq) * 17 + hk] = s * 0.125f;
    }
    __syncthreads();

    // softmax: 64 rows
    if (tid < 64) {
        float* row = sc + tid * 17;
        float mx = -1e30f;
#pragma unroll
        for (int j = 0; j < 16; ++j) mx = fmaxf(mx, row[j]);
        float sum = 0.f;
#pragma unroll
        for (int j = 0; j < 16; ++j) { float e = expf(row[j] - mx); row[j] = e; sum += e; }
        float inv = 1.f / sum;
#pragma unroll
        for (int j = 0; j < 16; ++j) row[j] *= inv;
    }
    __syncthreads();

    // out + scrambled fp16 store: 4096 -> 16 per thread
#pragma unroll
    for (int r = 0; r < 16; ++r) {
        int idx = tid + 256 * r;
        int tk = idx >> 10;
        int hq = (idx >> 6) & 15, d = idx & 63;
        const float* arow = sc + (tk*16 + hq) * 17;
        const float* vbase = vv + tk*16*PAD;
        float o = 0.f;
#pragma unroll
        for (int hk = 0; hk < 16; ++hk) o = fmaf(arow[hk], vbase[hk*PAD + d], o);
        int tg = tok0 + tk;
        int b = tg >> 13, t = tg & (TT - 1);
        size_t obase = ((size_t)b * TT + (t >> 4)) * (size_t)CC + (size_t)(t & 15) * DD;
        g_sh[obase + (size_t)hq * 512 * CC + d] = __float2half_rn(o);
    }
}

// ---------------------------------------------------------------------------
extern "C" void kernel_launch(void* const* d_in, const int* in_sizes, int n_in,
                              void* d_out, int out_size)
{
    const float* x    = (const float*)d_in[0];
    const float* Wqkv = (const float*)d_in[1];
    const float* Wout = (const float*)d_in[2];
    float* out = (float*)d_out;

    __half *qkv_p, *xh, *sh, *wqh, *woh;
    cudaGetSymbolAddress((void**)&qkv_p, g_qkv);
    cudaGetSymbolAddress((void**)&xh, g_xh);
    cudaGetSymbolAddress((void**)&sh, g_sh);
    cudaGetSymbolAddress((void**)&wqh, g_wqh);
    cudaGetSymbolAddress((void**)&woh, g_woh);

    int nsm = 148;
    cudaDeviceGetAttribute(&nsm, cudaDevAttrMultiProcessorCount, 0);

    cudaFuncSetAttribute(gemm_mma<__half>, cudaFuncAttributeMaxDynamicSharedMemorySize, GEMM_DYN);
    cudaFuncSetAttribute(gemm_mma<float>,  cudaFuncAttributeMaxDynamicSharedMemorySize, GEMM_DYN);
    cudaFuncSetAttribute(attn_kernel,      cudaFuncAttributeMaxDynamicSharedMemorySize, ATTN_DYN);

    rope_table_kernel<<<(TT*32 + 255) / 256, 256>>>();
    cvt_all_kernel<<<5120, 256>>>((const float4*)x, (const float4*)Wqkv, (const float4*)Wout,
                                  (uint2*)xh, (uint2*)wqh, (uint2*)woh);

    // GEMM1: qkv(fp16) = x @ Wqkv^T  (M=16384, N=3072, K=1024) — 1536 tiles
    {
        int ntiles = (QKVC / BN) * (MTOT / BM);
        int grid = ntiles < nsm ? ntiles : nsm;
        gemm_mma<__half><<<grid, 256, GEMM_DYN>>>(xh, wqh, qkv_p, QKVC, CC, QKVC / BN, ntiles);
    }

    // fused RoPE + head-attention + scramble (4 tokens/block)
    attn_kernel<<<MTOT / 4, 256, ATTN_DYN>>>();

    // GEMM2: out = scr @ Wout^T (M=16384, N=1024, K=1024) — 512 tiles
    {
        int ntiles = (CC / BN) * (MTOT / BM);
        int grid = ntiles < nsm ? ntiles : nsm;
        gemm_mma<float><<<grid, 256, GEMM_DYN>>>(sh, woh, out, CC, CC, CC / BN, ntiles);
    }
}

// round 15
// speedup vs baseline: 1.3085x; 1.0280x over previous
#include <cuda_runtime.h>
#include <cuda_fp16.h>
#include <math.h>
#include <stdint.h>

#define BB 2
#define TT 8192
#define CC 1024
#define HH 16
#define DD 64
#define MTOT (BB*TT)        // 16384
#define QKVC (3*CC)         // 3072

// ---------------- device scratch ----------------
__device__ __half g_qkv[(size_t)MTOT * QKVC];      // 96 MB fp16
__device__ __half g_xh[(size_t)MTOT * CC];
__device__ __half g_sh[(size_t)MTOT * CC];
__device__ __half g_wqh[(size_t)QKVC * CC];
__device__ __half g_woh[(size_t)CC * CC];
__device__ float g_cos[TT * 32];
__device__ float g_sin[TT * 32];

// ---------------- PTX helpers ----------------
__device__ __forceinline__ uint32_t smem_u32(const void* p) {
    uint32_t a;
    asm("{ .reg .u64 t; cvta.to.shared.u64 t, %1; cvt.u32.u64 %0, t; }" : "=r"(a) : "l"(p));
    return a;
}
__device__ __forceinline__ void cp16(uint32_t s, const void* g) {
    asm volatile("cp.async.cg.shared.global [%0], [%1], 16;" :: "r"(s), "l"(g));
}
#define CP_COMMIT() asm volatile("cp.async.commit_group;" ::: "memory")
#define CP_WAIT(n)  asm volatile("cp.async.wait_group %0;" :: "n"(n) : "memory")

__device__ __forceinline__ void ldsm_x4(uint32_t* r, uint32_t addr) {
    asm volatile("ldmatrix.sync.aligned.m8n8.x4.shared.b16 {%0,%1,%2,%3}, [%4];"
                 : "=r"(r[0]), "=r"(r[1]), "=r"(r[2]), "=r"(r[3]) : "r"(addr));
}
#define MMA_F16(d, a, b0, b1) \
    asm volatile("mma.sync.aligned.m16n8k16.row.col.f32.f16.f16.f32 " \
                 "{%0,%1,%2,%3}, {%4,%5,%6,%7}, {%8,%9}, {%0,%1,%2,%3};" \
                 : "+f"((d)[0]), "+f"((d)[1]), "+f"((d)[2]), "+f"((d)[3]) \
                 : "r"((a)[0]), "r"((a)[1]), "r"((a)[2]), "r"((a)[3]), \
                   "r"(b0), "r"(b1))

// ---------------- small kernels ----------------
__global__ void rope_table_kernel() {
    int idx = blockIdx.x * blockDim.x + threadIdx.x;
    if (idx >= TT * 32) return;
    int t = idx >> 5, d2 = idx & 31;
    float invf = (float)pow(10000.0, -(double)d2 / 32.0);
    float ang = __fmul_rn((float)t, invf);
    g_cos[idx] = (float)cos((double)ang);
    g_sin[idx] = (float)sin((double)ang);
}

// single merged fp32->fp16 convert for x, Wqkv, Wout (block quantum = 1024 float4)
__global__ void cvt_all_kernel(const float4* __restrict__ x,
                               const float4* __restrict__ wq,
                               const float4* __restrict__ wo,
                               uint2* __restrict__ xh,
                               uint2* __restrict__ wqh,
                               uint2* __restrict__ woh) {
    int blk = blockIdx.x;
    const float4* in;
    uint2* out;
    int base;
    if (blk < 4096)      { in = x;  out = xh;  base = blk * 1024; }
    else if (blk < 4864) { in = wq; out = wqh; base = (blk - 4096) * 1024; }
    else                 { in = wo; out = woh; base = (blk - 4864) * 1024; }
    int idx = base + threadIdx.x;
    float4 v[4];
#pragma unroll
    for (int k = 0; k < 4; ++k) v[k] = in[idx + k * 256];
#pragma unroll
    for (int k = 0; k < 4; ++k) {
        __half2 a = __floats2half2_rn(v[k].x, v[k].y);
        __half2 b = __floats2half2_rn(v[k].z, v[k].w);
        uint2 pk; pk.x = *(uint32_t*)&a; pk.y = *(uint32_t*)&b;
        out[idx + k * 256] = pk;
    }
}

// ---------------- persistent fp16 GEMM (NT) — R12/R14 best config ----------------
#define BM 128
#define BN 256
#define BKQ 64
#define KITER 16
#define T_A 0
#define T_B (16*1024)
#define STG  (48*1024)
#define NSTAGE 4
#define GEMM_DYN (NSTAGE*STG + 1024)

extern __shared__ char dynsmem[];

template <typename OutT>
__global__ __launch_bounds__(256, 1) void gemm_mma(
    const __half* __restrict__ Ah,
    const __half* __restrict__ Bh,
    OutT* __restrict__ C, int ldc, int K, int ntN, int ntiles)
{
    const int tid  = threadIdx.x;
    const int lane = tid & 31;
    const int wid  = tid >> 5;
    const int wm = (wid >> 2) * 64;
    const int wn = (wid & 3) * 64;
    const int bx = blockIdx.x;
    const int grid = gridDim.x;

    const int my_nt = (ntiles - 1 - bx) / grid + 1;
    const int my_iters = my_nt * KITER;

    uint32_t sbase = (smem_u32(dynsmem) + 1023u) & ~1023u;

    const int lrow = tid >> 1;
    const int lc4  = (tid & 1) * 4;
    uint32_t soffA[4], soffB1[4];
#pragma unroll
    for (int c = 0; c < 4; ++c) {
        uint32_t offA = (uint32_t)lrow * 128 + (uint32_t)(lc4 + c) * 16;
        soffA[c] = offA ^ ((offA >> 3) & 0x70);
        uint32_t offB1 = (uint32_t)(lrow + 128) * 128 + (uint32_t)(lc4 + c) * 16;
        soffB1[c] = offB1 ^ ((offB1 >> 3) & 0x70);
    }
    const int gcol = lc4 * 8;

    int ld_tile = bx;
    int ld_tm = ld_tile / ntN;
    int ld_tn = ld_tile - ld_tm * ntN;
    int ld_kk = 0;
    int ld_stage = 0;

    auto load_stage = [&]() {
        const __half* gA  = Ah + (size_t)(ld_tm * BM + lrow) * K + ld_kk * BKQ + gcol;
        const __half* gB0 = Bh + (size_t)(ld_tn * BN + lrow) * K + ld_kk * BKQ + gcol;
        const __half* gB1 = gB0 + (size_t)128 * K;
        uint32_t st = sbase + (uint32_t)(ld_stage & (NSTAGE - 1)) * STG;
#pragma unroll
        for (int c = 0; c < 4; ++c) {
            cp16(st + T_A + soffA[c],  gA  + c * 8);
            cp16(st + T_B + soffA[c],  gB0 + c * 8);
            cp16(st + T_B + soffB1[c], gB1 + c * 8);
        }
        CP_COMMIT();
        ++ld_stage;
        if (++ld_kk == KITER) {
            ld_kk = 0;
            ld_tile += grid;
            ld_tm = ld_tile / ntN;
            ld_tn = ld_tile - ld_tm * ntN;
        }
    };

    uint32_t a_rt[4], a_xr[4];
#pragma unroll
    for (int ti = 0; ti < 4; ++ti) {
        int r = wm + ti * 16 + (lane & 15);
        a_rt[ti] = (uint32_t)r * 128;
        a_xr[ti] = (uint32_t)(r & 7) << 4;
    }
    const uint32_t a_cb = (uint32_t)(lane >> 4) * 16;
    uint32_t b_rt[4], b_xr[4];
#pragma unroll
    for (int ni = 0; ni < 4; ++ni) {
        int r = wn + ni * 16 + (lane & 7) + (lane >> 4) * 8;
        b_rt[ni] = (uint32_t)r * 128;
        b_xr[ni] = (uint32_t)(r & 7) << 4;
    }
    const uint32_t b_cb = (uint32_t)((lane >> 3) & 1) * 16;

    float acc[4][8][4];
#pragma unroll
    for (int i = 0; i < 4; ++i)
#pragma unroll
        for (int j = 0; j < 8; ++j)
#pragma unroll
            for (int q = 0; q < 4; ++q) acc[i][j][q] = 0.f;

    load_stage();
    load_stage();

    for (int cp = 0; cp < my_iters; cp += 2) {
        CP_WAIT(0);
        __syncthreads();
        if (cp + 2 < my_iters) load_stage();
        if (cp + 3 < my_iters) load_stage();

        const uint32_t base0 = sbase + (uint32_t)((cp)     & (NSTAGE - 1)) * STG;
        const uint32_t base1 = sbase + (uint32_t)((cp + 1) & (NSTAGE - 1)) * STG;

        uint32_t ah[2][4][4], bh[2][4][4];
#pragma unroll
        for (int ni = 0; ni < 4; ++ni)
            ldsm_x4(bh[0][ni], base0 + T_B + b_rt[ni] + (b_cb ^ b_xr[ni]));
#pragma unroll
        for (int ti = 0; ti < 4; ++ti)
            ldsm_x4(ah[0][ti], base0 + T_A + a_rt[ti] + (a_cb ^ a_xr[ti]));

#pragma unroll
        for (int s = 0; s < 8; ++s) {
            const int cur = s & 1;
            const int nx  = cur ^ 1;
            if (s < 7) {
                const uint32_t bb = (s + 1 < 4) ? base0 : base1;
                const uint32_t kb = (uint32_t)((s + 1) & 3) * 32;
#pragma unroll
                for (int ni = 0; ni < 4; ++ni)
                    ldsm_x4(bh[nx][ni], bb + T_B + b_rt[ni] + ((b_cb + kb) ^ b_xr[ni]));
#pragma unroll
                for (int ti = 0; ti < 4; ++ti)
                    ldsm_x4(ah[nx][ti], bb + T_A + a_rt[ti] + ((a_cb + kb) ^ a_xr[ti]));
            }
#pragma unroll
            for (int mi = 0; mi < 4; ++mi)
#pragma unroll
                for (int ni = 0; ni < 4; ++ni) {
                    MMA_F16(acc[mi][2*ni],   ah[cur][mi], bh[cur][ni][0], bh[cur][ni][1]);
                    MMA_F16(acc[mi][2*ni+1], ah[cur][mi], bh[cur][ni][2], bh[cur][ni][3]);
                }
        }

        if (((cp + 1) & (KITER - 1)) == KITER - 1) {
            int tile = bx + ((cp + 1) >> 4) * grid;
            int tm = tile / ntN;
            int tn = tile - tm * ntN;
#pragma unroll
            for (int mi = 0; mi < 4; ++mi) {
                int gm = tm * BM + wm + mi * 16 + (lane >> 2);
#pragma unroll
                for (int ni = 0; ni < 8; ++ni) {
                    int gn = tn * BN + wn + ni * 8 + (lane & 3) * 2;
                    if constexpr (sizeof(OutT) == 4) {
                        float2 v0 = make_float2(acc[mi][ni][0], acc[mi][ni][1]);
                        float2 v1 = make_float2(acc[mi][ni][2], acc[mi][ni][3]);
                        *(float2*)((float*)C + (size_t)gm * ldc + gn) = v0;
                        *(float2*)((float*)C + (size_t)(gm + 8) * ldc + gn) = v1;
                    } else {
                        __half2 h0; h0.x = __float2half_rn(acc[mi][ni][0]); h0.y = __float2half_rn(acc[mi][ni][1]);
                        __half2 h1; h1.x = __float2half_rn(acc[mi][ni][2]); h1.y = __float2half_rn(acc[mi][ni][3]);
                        *(__half2*)((__half*)C + (size_t)gm * ldc + gn) = h0;
                        *(__half2*)((__half*)C + (size_t)(gm + 8) * ldc + gn) = h1;
                    }
                }
            }
#pragma unroll
            for (int i = 0; i < 4; ++i)
#pragma unroll
                for (int j = 0; j < 8; ++j)
#pragma unroll
                    for (int q = 0; q < 4; ++q) acc[i][j][q] = 0.f;
        }
    }
}

// ---------------- fused RoPE + 16x16 head-attn, 4 tokens/block, float4 smem ----------------
// PAD = 68 floats (= 17 float4) per row: 16B-aligned rows, conflict-free LDS.128.
// layout (floats): q[64][68] | k | v | sc[64][17] | cs[4][32] | sn[4][32]
#define PAD 68
#define PAD4 17
#define AQ_OFF 0
#define AK_OFF 4352
#define AV_OFF 8704
#define ASC_OFF 13056
#define ACS_OFF 14144
#define ASN_OFF 14272
#define ATTN_DYN (14400 * 4)

__global__ __launch_bounds__(256) void attn_kernel()
{
    float* sm = (float*)dynsmem;
    float* q  = sm + AQ_OFF;
    float* kk = sm + AK_OFF;
    float* vv = sm + AV_OFF;
    float* sc = sm + ASC_OFF;
    float* cs = sm + ACS_OFF;
    float* sn = sm + ASN_OFF;
    float4* q4 = (float4*)q;
    float4* k4 = (float4*)kk;
    float4* v4 = (float4*)vv;

    const int tok0 = blockIdx.x * 4;
    const int tid = threadIdx.x;

    if (tid < 128) {
        int tk = tid >> 5, d2 = tid & 31;
        int t = (tok0 + tk) & (TT - 1);
        cs[tk*32 + d2] = g_cos[t*32 + d2];
        sn[tk*32 + d2] = g_sin[t*32 + d2];
    }

    // ---- load 4 tokens x 3072 halfs = 1536 float4(half8), 6/thread; float4 smem stores
    const float4* base = (const float4*)(g_qkv + (size_t)tok0 * QKVC);
#pragma unroll
    for (int r = 0; r < 6; ++r) {
        int id = r * 256 + tid;          // 0..1535
        float4 raw = base[id];
        int tk = id / 384;
        int f  = id - tk * 384;          // 0..383
        int s  = f >> 7;                 // 0=q 1=k 2=v
        int h  = (f >> 3) & 15;
        int d0 = (f & 7) * 8;
        float* dst = (s == 0 ? q : s == 1 ? kk : vv) + (tk*16 + h) * PAD + d0;
        const __half2* hp = (const __half2*)&raw;
        float2 f0 = __half22float2(hp[0]);
        float2 f1 = __half22float2(hp[1]);
        float2 f2 = __half22float2(hp[2]);
        float2 f3 = __half22float2(hp[3]);
        *(float4*)dst       = make_float4(f0.x, f0.y, f1.x, f1.y);
        *(float4*)(dst + 4) = make_float4(f2.x, f2.y, f3.x, f3.y);
    }
    __syncthreads();

    // ---- RoPE: 4 tok x (q,k) x 16 heads x 16 float4-groups (2 pairs each) = 2048 -> 8/thread
#pragma unroll
    for (int r = 0; r < 8; ++r) {
        int idx = tid + 256 * r;         // 0..2047
        int tk = idx >> 9;
        int which = (idx >> 8) & 1;
        int h = (idx >> 4) & 15;
        int g = idx & 15;                // float4 group: pairs 2g, 2g+1
        float c0 = cs[tk*32 + 2*g],     s0 = sn[tk*32 + 2*g];
        float c1 = cs[tk*32 + 2*g + 1], s1 = sn[tk*32 + 2*g + 1];
        float4* p = (float4*)((which ? kk : q) + (tk*16 + h) * PAD) + g;
        float4 v = *p;
        float4 o;
        o.x = v.x*c0 - v.y*s0;
        o.y = v.y*c0 + v.x*s0;
        o.z = v.z*c1 - v.w*s1;
        o.w = v.w*c1 + v.z*s1;
        *p = o;
    }
    __syncthreads();

    // ---- scores: 1024 (tk,hq,hk) -> 4/thread, float4 dot over d
#pragma unroll
    for (int r = 0; r < 4; ++r) {
        int idx = tid + 256 * r;
        int tk = idx >> 8;
        int hq = (idx >> 4) & 15, hk = idx & 15;
        const float4* qr = q4 + (tk*16 + hq) * PAD4;
        const float4* kr = k4 + (tk*16 + hk) * PAD4;
        float s = 0.f;
#pragma unroll
        for (int d4 = 0; d4 < 16; ++d4) {
            float4 a = qr[d4], b = kr[d4];
            s = fmaf(a.x, b.x, s); s = fmaf(a.y, b.y, s);
            s = fmaf(a.z, b.z, s); s = fmaf(a.w, b.w, s);
        }
        sc[(tk*16 + hq) * 17 + hk] = s * 0.125f;
    }
    __syncthreads();

    // ---- softmax: 64 rows
    if (tid < 64) {
        float* row = sc + tid * 17;
        float mx = -1e30f;
#pragma unroll
        for (int j = 0; j < 16; ++j) mx = fmaxf(mx, row[j]);
        float sum = 0.f;
#pragma unroll
        for (int j = 0; j < 16; ++j) { float e = expf(row[j] - mx); row[j] = e; sum += e; }
        float inv = 1.f / sum;
#pragma unroll
        for (int j = 0; j < 16; ++j) row[j] *= inv;
    }
    __syncthreads();

    // ---- out: 1024 (tk,hq,d4) quads -> 4/thread; fp16x4 scrambled store
#pragma unroll
    for (int r = 0; r < 4; ++r) {
        int idx = tid + 256 * r;
        int tk = idx >> 8;
        int hq = (idx >> 4) & 15, d4 = idx & 15;
        const float* arow = sc + (tk*16 + hq) * 17;
        const float4* vb = v4 + (tk*16) * PAD4 + d4;
        float4 o = make_float4(0.f, 0.f, 0.f, 0.f);
#pragma unroll
        for (int hk = 0; hk < 16; ++hk) {
            float w = arow[hk];
            float4 vv4 = vb[hk * PAD4];
            o.x = fmaf(w, vv4.x, o.x);
            o.y = fmaf(w, vv4.y, o.y);
            o.z = fmaf(w, vv4.z, o.z);
            o.w = fmaf(w, vv4.w, o.w);
        }
        int tg = tok0 + tk;
        int b = tg >> 13, t = tg & (TT - 1);
        size_t obase = ((size_t)b * TT + (t >> 4)) * (size_t)CC + (size_t)(t & 15) * DD;
        __half2 h0 = __floats2half2_rn(o.x, o.y);
        __half2 h1 = __floats2half2_rn(o.z, o.w);
        uint2 pk; pk.x = *(uint32_t*)&h0; pk.y = *(uint32_t*)&h1;
        *(uint2*)(g_sh + obase + (size_t)hq * 512 * CC + d4 * 4) = pk;
    }
}

// ---------------------------------------------------------------------------
extern "C" void kernel_launch(void* const* d_in, const int* in_sizes, int n_in,
                              void* d_out, int out_size)
{
    const float* x    = (const float*)d_in[0];
    const float* Wqkv = (const float*)d_in[1];
    const float* Wout = (const float*)d_in[2];
    float* out = (float*)d_out;

    __half *qkv_p, *xh, *sh, *wqh, *woh;
    cudaGetSymbolAddress((void**)&qkv_p, g_qkv);
    cudaGetSymbolAddress((void**)&xh, g_xh);
    cudaGetSymbolAddress((void**)&sh, g_sh);
    cudaGetSymbolAddress((void**)&wqh, g_wqh);
    cudaGetSymbolAddress((void**)&woh, g_woh);

    int nsm = 148;
    cudaDeviceGetAttribute(&nsm, cudaDevAttrMultiProcessorCount, 0);

    cudaFuncSetAttribute(gemm_mma<__half>, cudaFuncAttributeMaxDynamicSharedMemorySize, GEMM_DYN);
    cudaFuncSetAttribute(gemm_mma<float>,  cudaFuncAttributeMaxDynamicSharedMemorySize, GEMM_DYN);
    cudaFuncSetAttribute(attn_kernel,      cudaFuncAttributeMaxDynamicSharedMemorySize, ATTN_DYN);

    rope_table_kernel<<<(TT*32 + 255) / 256, 256>>>();
    cvt_all_kernel<<<5120, 256>>>((const float4*)x, (const float4*)Wqkv, (const float4*)Wout,
                                  (uint2*)xh, (uint2*)wqh, (uint2*)woh);

    // GEMM1: qkv(fp16) = x @ Wqkv^T  (M=16384, N=3072, K=1024)
    {
        int ntiles = (QKVC / BN) * (MTOT / BM);
        int grid = ntiles < nsm ? ntiles : nsm;
        gemm_mma<__half><<<grid, 256, GEMM_DYN>>>(xh, wqh, qkv_p, QKVC, CC, QKVC / BN, ntiles);
    }

    // fused RoPE + head-attention + scramble (4 tokens/block, vectorized)
    attn_kernel<<<MTOT / 4, 256, ATTN_DYN>>>();

    // GEMM2: out = scr @ Wout^T (M=16384, N=1024, K=1024)
    {
        int ntiles = (CC / BN) * (MTOT / BM);
        int grid = ntiles < nsm ? ntiles : nsm;
        gemm_mma<float><<<grid, 256, GEMM_DYN>>>(sh, woh, out, CC, CC, CC / BN, ntiles);
    }
}

// round 16
// speedup vs baseline: 1.3419x; 1.0255x over previous
#include <cuda_runtime.h>
#include <cuda_fp16.h>
#include <math.h>
#include <stdint.h>

#define BB 2
#define TT 8192
#define CC 1024
#define HH 16
#define DD 64
#define MTOT (BB*TT)        // 16384
#define QKVC (3*CC)         // 3072

// ---------------- device scratch ----------------
__device__ __half g_qkv[(size_t)MTOT * QKVC];      // 96 MB fp16
__device__ __half g_xh[(size_t)MTOT * CC];
__device__ __half g_sh[(size_t)MTOT * CC];
__device__ __half g_wqh[(size_t)QKVC * CC];
__device__ __half g_woh[(size_t)CC * CC];
__device__ float g_cos[TT * 32];
__device__ float g_sin[TT * 32];

// ---------------- PTX helpers ----------------
__device__ __forceinline__ uint32_t smem_u32(const void* p) {
    uint32_t a;
    asm("{ .reg .u64 t; cvta.to.shared.u64 t, %1; cvt.u32.u64 %0, t; }" : "=r"(a) : "l"(p));
    return a;
}
__device__ __forceinline__ void cp16(uint32_t s, const void* g) {
    asm volatile("cp.async.cg.shared.global [%0], [%1], 16;" :: "r"(s), "l"(g));
}
#define CP_COMMIT() asm volatile("cp.async.commit_group;" ::: "memory")
#define CP_WAIT(n)  asm volatile("cp.async.wait_group %0;" :: "n"(n) : "memory")

__device__ __forceinline__ void ldsm_x4(uint32_t* r, uint32_t addr) {
    asm volatile("ldmatrix.sync.aligned.m8n8.x4.shared.b16 {%0,%1,%2,%3}, [%4];"
                 : "=r"(r[0]), "=r"(r[1]), "=r"(r[2]), "=r"(r[3]) : "r"(addr));
}
#define MMA_F16(d, a, b0, b1) \
    asm volatile("mma.sync.aligned.m16n8k16.row.col.f32.f16.f16.f32 " \
                 "{%0,%1,%2,%3}, {%4,%5,%6,%7}, {%8,%9}, {%0,%1,%2,%3};" \
                 : "+f"((d)[0]), "+f"((d)[1]), "+f"((d)[2]), "+f"((d)[3]) \
                 : "r"((a)[0]), "r"((a)[1]), "r"((a)[2]), "r"((a)[3]), \
                   "r"(b0), "r"(b1))

// ---------------- small kernels ----------------
__global__ void rope_table_kernel() {
    int idx = blockIdx.x * blockDim.x + threadIdx.x;
    if (idx >= TT * 32) return;
    int t = idx >> 5, d2 = idx & 31;
    float invf = (float)pow(10000.0, -(double)d2 / 32.0);
    float ang = __fmul_rn((float)t, invf);
    g_cos[idx] = (float)cos((double)ang);
    g_sin[idx] = (float)sin((double)ang);
}

__global__ void cvt_all_kernel(const float4* __restrict__ x,
                               const float4* __restrict__ wq,
                               const float4* __restrict__ wo,
                               uint2* __restrict__ xh,
                               uint2* __restrict__ wqh,
                               uint2* __restrict__ woh) {
    int blk = blockIdx.x;
    const float4* in;
    uint2* out;
    int base;
    if (blk < 4096)      { in = x;  out = xh;  base = blk * 1024; }
    else if (blk < 4864) { in = wq; out = wqh; base = (blk - 4096) * 1024; }
    else                 { in = wo; out = woh; base = (blk - 4864) * 1024; }
    int idx = base + threadIdx.x;
    float4 v[4];
#pragma unroll
    for (int k = 0; k < 4; ++k) v[k] = in[idx + k * 256];
#pragma unroll
    for (int k = 0; k < 4; ++k) {
        __half2 a = __floats2half2_rn(v[k].x, v[k].y);
        __half2 b = __floats2half2_rn(v[k].z, v[k].w);
        uint2 pk; pk.x = *(uint32_t*)&a; pk.y = *(uint32_t*)&b;
        out[idx + k * 256] = pk;
    }
}

// ---------------- persistent fp16 GEMM (NT) — best config (frozen) ----------------
#define BM 128
#define BN 256
#define BKQ 64
#define KITER 16
#define T_A 0
#define T_B (16*1024)
#define STG  (48*1024)
#define NSTAGE 4
#define GEMM_DYN (NSTAGE*STG + 1024)

extern __shared__ char dynsmem[];

template <typename OutT>
__global__ __launch_bounds__(256, 1) void gemm_mma(
    const __half* __restrict__ Ah,
    const __half* __restrict__ Bh,
    OutT* __restrict__ C, int ldc, int K, int ntN, int ntiles)
{
    const int tid  = threadIdx.x;
    const int lane = tid & 31;
    const int wid  = tid >> 5;
    const int wm = (wid >> 2) * 64;
    const int wn = (wid & 3) * 64;
    const int bx = blockIdx.x;
    const int grid = gridDim.x;

    const int my_nt = (ntiles - 1 - bx) / grid + 1;
    const int my_iters = my_nt * KITER;

    uint32_t sbase = (smem_u32(dynsmem) + 1023u) & ~1023u;

    const int lrow = tid >> 1;
    const int lc4  = (tid & 1) * 4;
    uint32_t soffA[4], soffB1[4];
#pragma unroll
    for (int c = 0; c < 4; ++c) {
        uint32_t offA = (uint32_t)lrow * 128 + (uint32_t)(lc4 + c) * 16;
        soffA[c] = offA ^ ((offA >> 3) & 0x70);
        uint32_t offB1 = (uint32_t)(lrow + 128) * 128 + (uint32_t)(lc4 + c) * 16;
        soffB1[c] = offB1 ^ ((offB1 >> 3) & 0x70);
    }
    const int gcol = lc4 * 8;

    int ld_tile = bx;
    int ld_tm = ld_tile / ntN;
    int ld_tn = ld_tile - ld_tm * ntN;
    int ld_kk = 0;
    int ld_stage = 0;

    auto load_stage = [&]() {
        const __half* gA  = Ah + (size_t)(ld_tm * BM + lrow) * K + ld_kk * BKQ + gcol;
        const __half* gB0 = Bh + (size_t)(ld_tn * BN + lrow) * K + ld_kk * BKQ + gcol;
        const __half* gB1 = gB0 + (size_t)128 * K;
        uint32_t st = sbase + (uint32_t)(ld_stage & (NSTAGE - 1)) * STG;
#pragma unroll
        for (int c = 0; c < 4; ++c) {
            cp16(st + T_A + soffA[c],  gA  + c * 8);
            cp16(st + T_B + soffA[c],  gB0 + c * 8);
            cp16(st + T_B + soffB1[c], gB1 + c * 8);
        }
        CP_COMMIT();
        ++ld_stage;
        if (++ld_kk == KITER) {
            ld_kk = 0;
            ld_tile += grid;
            ld_tm = ld_tile / ntN;
            ld_tn = ld_tile - ld_tm * ntN;
        }
    };

    uint32_t a_rt[4], a_xr[4];
#pragma unroll
    for (int ti = 0; ti < 4; ++ti) {
        int r = wm + ti * 16 + (lane & 15);
        a_rt[ti] = (uint32_t)r * 128;
        a_xr[ti] = (uint32_t)(r & 7) << 4;
    }
    const uint32_t a_cb = (uint32_t)(lane >> 4) * 16;
    uint32_t b_rt[4], b_xr[4];
#pragma unroll
    for (int ni = 0; ni < 4; ++ni) {
        int r = wn + ni * 16 + (lane & 7) + (lane >> 4) * 8;
        b_rt[ni] = (uint32_t)r * 128;
        b_xr[ni] = (uint32_t)(r & 7) << 4;
    }
    const uint32_t b_cb = (uint32_t)((lane >> 3) & 1) * 16;

    float acc[4][8][4];
#pragma unroll
    for (int i = 0; i < 4; ++i)
#pragma unroll
        for (int j = 0; j < 8; ++j)
#pragma unroll
            for (int q = 0; q < 4; ++q) acc[i][j][q] = 0.f;

    load_stage();
    load_stage();

    for (int cp = 0; cp < my_iters; cp += 2) {
        CP_WAIT(0);
        __syncthreads();
        if (cp + 2 < my_iters) load_stage();
        if (cp + 3 < my_iters) load_stage();

        const uint32_t base0 = sbase + (uint32_t)((cp)     & (NSTAGE - 1)) * STG;
        const uint32_t base1 = sbase + (uint32_t)((cp + 1) & (NSTAGE - 1)) * STG;

        uint32_t ah[2][4][4], bh[2][4][4];
#pragma unroll
        for (int ni = 0; ni < 4; ++ni)
            ldsm_x4(bh[0][ni], base0 + T_B + b_rt[ni] + (b_cb ^ b_xr[ni]));
#pragma unroll
        for (int ti = 0; ti < 4; ++ti)
            ldsm_x4(ah[0][ti], base0 + T_A + a_rt[ti] + (a_cb ^ a_xr[ti]));

#pragma unroll
        for (int s = 0; s < 8; ++s) {
            const int cur = s & 1;
            const int nx  = cur ^ 1;
            if (s < 7) {
                const uint32_t bb = (s + 1 < 4) ? base0 : base1;
                const uint32_t kb = (uint32_t)((s + 1) & 3) * 32;
#pragma unroll
                for (int ni = 0; ni < 4; ++ni)
                    ldsm_x4(bh[nx][ni], bb + T_B + b_rt[ni] + ((b_cb + kb) ^ b_xr[ni]));
#pragma unroll
                for (int ti = 0; ti < 4; ++ti)
                    ldsm_x4(ah[nx][ti], bb + T_A + a_rt[ti] + ((a_cb + kb) ^ a_xr[ti]));
            }
#pragma unroll
            for (int mi = 0; mi < 4; ++mi)
#pragma unroll
                for (int ni = 0; ni < 4; ++ni) {
                    MMA_F16(acc[mi][2*ni],   ah[cur][mi], bh[cur][ni][0], bh[cur][ni][1]);
                    MMA_F16(acc[mi][2*ni+1], ah[cur][mi], bh[cur][ni][2], bh[cur][ni][3]);
                }
        }

        if (((cp + 1) & (KITER - 1)) == KITER - 1) {
            int tile = bx + ((cp + 1) >> 4) * grid;
            int tm = tile / ntN;
            int tn = tile - tm * ntN;
#pragma unroll
            for (int mi = 0; mi < 4; ++mi) {
                int gm = tm * BM + wm + mi * 16 + (lane >> 2);
#pragma unroll
                for (int ni = 0; ni < 8; ++ni) {
                    int gn = tn * BN + wn + ni * 8 + (lane & 3) * 2;
                    if constexpr (sizeof(OutT) == 4) {
                        float2 v0 = make_float2(acc[mi][ni][0], acc[mi][ni][1]);
                        float2 v1 = make_float2(acc[mi][ni][2], acc[mi][ni][3]);
                        *(float2*)((float*)C + (size_t)gm * ldc + gn) = v0;
                        *(float2*)((float*)C + (size_t)(gm + 8) * ldc + gn) = v1;
                    } else {
                        __half2 h0; h0.x = __float2half_rn(acc[mi][ni][0]); h0.y = __float2half_rn(acc[mi][ni][1]);
                        __half2 h1; h1.x = __float2half_rn(acc[mi][ni][2]); h1.y = __float2half_rn(acc[mi][ni][3]);
                        *(__half2*)((__half*)C + (size_t)gm * ldc + gn) = h0;
                        *(__half2*)((__half*)C + (size_t)(gm + 8) * ldc + gn) = h1;
                    }
                }
            }
#pragma unroll
            for (int i = 0; i < 4; ++i)
#pragma unroll
                for (int j = 0; j < 8; ++j)
#pragma unroll
                    for (int q = 0; q < 4; ++q) acc[i][j][q] = 0.f;
        }
    }
}

// ---------------- fused RoPE + 16x16 head-attn, 4 tokens/block ----------------
// Register-blocked scores (4x4 + d-split across 4 lanes) and out (4hq x 1d4).
#define PAD 68
#define PAD4 17
#define AQ_OFF 0
#define AK_OFF 4352
#define AV_OFF 8704
#define ASC_OFF 13056
#define ACS_OFF 14144
#define ASN_OFF 14272
#define ATTN_DYN (14400 * 4)

__global__ __launch_bounds__(256) void attn_kernel()
{
    float* sm = (float*)dynsmem;
    float* q  = sm + AQ_OFF;
    float* kk = sm + AK_OFF;
    float* vv = sm + AV_OFF;
    float* sc = sm + ASC_OFF;
    float* cs = sm + ACS_OFF;
    float* sn = sm + ASN_OFF;
    float4* q4 = (float4*)q;
    float4* k4 = (float4*)kk;
    float4* v4 = (float4*)vv;

    const int tok0 = blockIdx.x * 4;
    const int tid = threadIdx.x;

    if (tid < 128) {
        int tk = tid >> 5, d2 = tid & 31;
        int t = (tok0 + tk) & (TT - 1);
        cs[tk*32 + d2] = g_cos[t*32 + d2];
        sn[tk*32 + d2] = g_sin[t*32 + d2];
    }

    // ---- load 4 tokens x 3072 halfs, float4 stores
    const float4* base = (const float4*)(g_qkv + (size_t)tok0 * QKVC);
#pragma unroll
    for (int r = 0; r < 6; ++r) {
        int id = r * 256 + tid;
        float4 raw = base[id];
        int tk = id / 384;
        int f  = id - tk * 384;
        int s  = f >> 7;
        int h  = (f >> 3) & 15;
        int d0 = (f & 7) * 8;
        float* dst = (s == 0 ? q : s == 1 ? kk : vv) + (tk*16 + h) * PAD + d0;
        const __half2* hp = (const __half2*)&raw;
        float2 f0 = __half22float2(hp[0]);
        float2 f1 = __half22float2(hp[1]);
        float2 f2 = __half22float2(hp[2]);
        float2 f3 = __half22float2(hp[3]);
        *(float4*)dst       = make_float4(f0.x, f0.y, f1.x, f1.y);
        *(float4*)(dst + 4) = make_float4(f2.x, f2.y, f3.x, f3.y);
    }
    __syncthreads();

    // ---- RoPE (float4, 8/thread)
#pragma unroll
    for (int r = 0; r < 8; ++r) {
        int idx = tid + 256 * r;
        int tk = idx >> 9;
        int which = (idx >> 8) & 1;
        int h = (idx >> 4) & 15;
        int g = idx & 15;
        float c0 = cs[tk*32 + 2*g],     s0 = sn[tk*32 + 2*g];
        float c1 = cs[tk*32 + 2*g + 1], s1 = sn[tk*32 + 2*g + 1];
        float4* p = (float4*)((which ? kk : q) + (tk*16 + h) * PAD) + g;
        float4 v = *p;
        float4 o;
        o.x = v.x*c0 - v.y*s0;
        o.y = v.y*c0 + v.x*s0;
        o.z = v.z*c1 - v.w*s1;
        o.w = v.w*c1 + v.z*s1;
        *p = o;
    }
    __syncthreads();

    // ---- scores: 4x4 register block, d split across 4 adjacent lanes
    {
        int tk  = tid >> 6;
        int bi  = (tid >> 2) & 15;      // 4x4 block index
        int dq  = tid & 3;              // d quarter
        int hq0 = (bi >> 2) * 4;
        int hk0 = (bi & 3) * 4;
        const float4* qb = q4 + (tk*16 + hq0) * PAD4 + dq * 4;
        const float4* kb = k4 + (tk*16 + hk0) * PAD4 + dq * 4;
        float s[4][4];
#pragma unroll
        for (int i = 0; i < 4; ++i)
#pragma unroll
            for (int j = 0; j < 4; ++j) s[i][j] = 0.f;
#pragma unroll
        for (int it = 0; it < 4; ++it) {
            float4 qa[4], ka[4];
#pragma unroll
            for (int i = 0; i < 4; ++i) qa[i] = qb[i * PAD4 + it];
#pragma unroll
            for (int j = 0; j < 4; ++j) ka[j] = kb[j * PAD4 + it];
#pragma unroll
            for (int i = 0; i < 4; ++i)
#pragma unroll
                for (int j = 0; j < 4; ++j) {
                    s[i][j] = fmaf(qa[i].x, ka[j].x, s[i][j]);
                    s[i][j] = fmaf(qa[i].y, ka[j].y, s[i][j]);
                    s[i][j] = fmaf(qa[i].z, ka[j].z, s[i][j]);
                    s[i][j] = fmaf(qa[i].w, ka[j].w, s[i][j]);
                }
        }
#pragma unroll
        for (int i = 0; i < 4; ++i)
#pragma unroll
            for (int j = 0; j < 4; ++j) {
                float v = s[i][j];
                v += __shfl_xor_sync(0xffffffffu, v, 1);
                v += __shfl_xor_sync(0xffffffffu, v, 2);
                s[i][j] = v;
            }
        if (dq == 0) {
#pragma unroll
            for (int i = 0; i < 4; ++i)
#pragma unroll
                for (int j = 0; j < 4; ++j)
                    sc[(tk*16 + hq0 + i) * 17 + hk0 + j] = s[i][j] * 0.125f;
        }
    }
    __syncthreads();

    // ---- softmax: 64 rows
    if (tid < 64) {
        float* row = sc + tid * 17;
        float mx = -1e30f;
#pragma unroll
        for (int j = 0; j < 16; ++j) mx = fmaxf(mx, row[j]);
        float sum = 0.f;
#pragma unroll
        for (int j = 0; j < 16; ++j) { float e = expf(row[j] - mx); row[j] = e; sum += e; }
        float inv = 1.f / sum;
#pragma unroll
        for (int j = 0; j < 16; ++j) row[j] *= inv;
    }
    __syncthreads();

    // ---- out: each thread computes 4 hq x 1 d4 (v float4 reused x4)
    {
        int tk  = tid >> 6;
        int hqg = (tid >> 4) & 3;
        int d4  = tid & 15;
        int hq0 = hqg * 4;
        const float4* vb = v4 + (tk*16) * PAD4 + d4;
        const float* srow = sc + (tk*16 + hq0) * 17;
        float4 o[4];
#pragma unroll
        for (int i = 0; i < 4; ++i) o[i] = make_float4(0.f, 0.f, 0.f, 0.f);
#pragma unroll
        for (int hk = 0; hk < 16; ++hk) {
            float4 vv4 = vb[hk * PAD4];
#pragma unroll
            for (int i = 0; i < 4; ++i) {
                float w = srow[i * 17 + hk];
                o[i].x = fmaf(w, vv4.x, o[i].x);
                o[i].y = fmaf(w, vv4.y, o[i].y);
                o[i].z = fmaf(w, vv4.z, o[i].z);
                o[i].w = fmaf(w, vv4.w, o[i].w);
            }
        }
        int tg = tok0 + tk;
        int b = tg >> 13, t = tg & (TT - 1);
        size_t obase = ((size_t)b * TT + (t >> 4)) * (size_t)CC + (size_t)(t & 15) * DD + (size_t)d4 * 4;
#pragma unroll
        for (int i = 0; i < 4; ++i) {
            __half2 h0 = __floats2half2_rn(o[i].x, o[i].y);
            __half2 h1 = __floats2half2_rn(o[i].z, o[i].w);
            uint2 pk; pk.x = *(uint32_t*)&h0; pk.y = *(uint32_t*)&h1;
            *(uint2*)(g_sh + obase + (size_t)(hq0 + i) * 512 * CC) = pk;
        }
    }
}

// ---------------------------------------------------------------------------
extern "C" void kernel_launch(void* const* d_in, const int* in_sizes, int n_in,
                              void* d_out, int out_size)
{
    const float* x    = (const float*)d_in[0];
    const float* Wqkv = (const float*)d_in[1];
    const float* Wout = (const float*)d_in[2];
    float* out = (float*)d_out;

    __half *qkv_p, *xh, *sh, *wqh, *woh;
    cudaGetSymbolAddress((void**)&qkv_p, g_qkv);
    cudaGetSymbolAddress((void**)&xh, g_xh);
    cudaGetSymbolAddress((void**)&sh, g_sh);
    cudaGetSymbolAddress((void**)&wqh, g_wqh);
    cudaGetSymbolAddress((void**)&woh, g_woh);

    int nsm = 148;
    cudaDeviceGetAttribute(&nsm, cudaDevAttrMultiProcessorCount, 0);

    cudaFuncSetAttribute(gemm_mma<__half>, cudaFuncAttributeMaxDynamicSharedMemorySize, GEMM_DYN);
    cudaFuncSetAttribute(gemm_mma<float>,  cudaFuncAttributeMaxDynamicSharedMemorySize, GEMM_DYN);
    cudaFuncSetAttribute(attn_kernel,      cudaFuncAttributeMaxDynamicSharedMemorySize, ATTN_DYN);

    rope_table_kernel<<<(TT*32 + 255) / 256, 256>>>();
    cvt_all_kernel<<<5120, 256>>>((const float4*)x, (const float4*)Wqkv, (const float4*)Wout,
                                  (uint2*)xh, (uint2*)wqh, (uint2*)woh);

    // GEMM1: qkv(fp16) = x @ Wqkv^T  (M=16384, N=3072, K=1024)
    {
        int ntiles = (QKVC / BN) * (MTOT / BM);
        int grid = ntiles < nsm ? ntiles : nsm;
        gemm_mma<__half><<<grid, 256, GEMM_DYN>>>(xh, wqh, qkv_p, QKVC, CC, QKVC / BN, ntiles);
    }

    // fused RoPE + head-attention + scramble (register-blocked)
    attn_kernel<<<MTOT / 4, 256, ATTN_DYN>>>();

    // GEMM2: out = scr @ Wout^T (M=16384, N=1024, K=1024)
    {
        int ntiles = (CC / BN) * (MTOT / BM);
        int grid = ntiles < nsm ? ntiles : nsm;
        gemm_mma<float><<<grid, 256, GEMM_DYN>>>(sh, woh, out, CC, CC, CC / BN, ntiles);
    }
}

// round 17
// speedup vs baseline: 1.4189x; 1.0574x over previous
#include <cuda_runtime.h>
#include <cuda_fp16.h>
#include <math.h>
#include <stdint.h>

#define BB 2
#define TT 8192
#define CC 1024
#define HH 16
#define DD 64
#define MTOT (BB*TT)        // 16384
#define QKVC (3*CC)         // 3072

// ---------------- device scratch ----------------
__device__ __half g_qkv[(size_t)MTOT * QKVC];      // 96 MB fp16
__device__ __half g_xh[(size_t)MTOT * CC];
__device__ __half g_sh[(size_t)MTOT * CC];
__device__ __half g_wqh[(size_t)QKVC * CC];
__device__ __half g_woh[(size_t)CC * CC];
__device__ float g_cos[TT * 32];
__device__ float g_sin[TT * 32];

// ---------------- PTX helpers ----------------
__device__ __forceinline__ uint32_t smem_u32(const void* p) {
    uint32_t a;
    asm("{ .reg .u64 t; cvta.to.shared.u64 t, %1; cvt.u32.u64 %0, t; }" : "=r"(a) : "l"(p));
    return a;
}
__device__ __forceinline__ void cp16(uint32_t s, const void* g) {
    asm volatile("cp.async.cg.shared.global [%0], [%1], 16;" :: "r"(s), "l"(g));
}
#define CP_COMMIT() asm volatile("cp.async.commit_group;" ::: "memory")
#define CP_WAIT(n)  asm volatile("cp.async.wait_group %0;" :: "n"(n) : "memory")

__device__ __forceinline__ void ldsm_x4(uint32_t* r, uint32_t addr) {
    asm volatile("ldmatrix.sync.aligned.m8n8.x4.shared.b16 {%0,%1,%2,%3}, [%4];"
                 : "=r"(r[0]), "=r"(r[1]), "=r"(r[2]), "=r"(r[3]) : "r"(addr));
}
#define MMA_F16(d, a, b0, b1) \
    asm volatile("mma.sync.aligned.m16n8k16.row.col.f32.f16.f16.f32 " \
                 "{%0,%1,%2,%3}, {%4,%5,%6,%7}, {%8,%9}, {%0,%1,%2,%3};" \
                 : "+f"((d)[0]), "+f"((d)[1]), "+f"((d)[2]), "+f"((d)[3]) \
                 : "r"((a)[0]), "r"((a)[1]), "r"((a)[2]), "r"((a)[3]), \
                   "r"(b0), "r"(b1))

// ---------------- small kernels ----------------
__global__ void rope_table_kernel() {
    int idx = blockIdx.x * blockDim.x + threadIdx.x;
    if (idx >= TT * 32) return;
    int t = idx >> 5, d2 = idx & 31;
    float invf = (float)pow(10000.0, -(double)d2 / 32.0);
    float ang = __fmul_rn((float)t, invf);
    g_cos[idx] = (float)cos((double)ang);
    g_sin[idx] = (float)sin((double)ang);
}

__global__ void cvt_all_kernel(const float4* __restrict__ x,
                               const float4* __restrict__ wq,
                               const float4* __restrict__ wo,
                               uint2* __restrict__ xh,
                               uint2* __restrict__ wqh,
                               uint2* __restrict__ woh) {
    int blk = blockIdx.x;
    const float4* in;
    uint2* out;
    int base;
    if (blk < 4096)      { in = x;  out = xh;  base = blk * 1024; }
    else if (blk < 4864) { in = wq; out = wqh; base = (blk - 4096) * 1024; }
    else                 { in = wo; out = woh; base = (blk - 4864) * 1024; }
    int idx = base + threadIdx.x;
    float4 v[4];
#pragma unroll
    for (int k = 0; k < 4; ++k) v[k] = in[idx + k * 256];
#pragma unroll
    for (int k = 0; k < 4; ++k) {
        __half2 a = __floats2half2_rn(v[k].x, v[k].y);
        __half2 b = __floats2half2_rn(v[k].z, v[k].w);
        uint2 pk; pk.x = *(uint32_t*)&a; pk.y = *(uint32_t*)&b;
        out[idx + k * 256] = pk;
    }
}

// ---------------- persistent fp16 GEMM (NT) — best config (frozen) ----------------
#define BM 128
#define BN 256
#define BKQ 64
#define KITER 16
#define T_A 0
#define T_B (16*1024)
#define STG  (48*1024)
#define NSTAGE 4
#define GEMM_DYN (NSTAGE*STG + 1024)

extern __shared__ char dynsmem[];

template <typename OutT>
__global__ __launch_bounds__(256, 1) void gemm_mma(
    const __half* __restrict__ Ah,
    const __half* __restrict__ Bh,
    OutT* __restrict__ C, int ldc, int K, int ntN, int ntiles)
{
    const int tid  = threadIdx.x;
    const int lane = tid & 31;
    const int wid  = tid >> 5;
    const int wm = (wid >> 2) * 64;
    const int wn = (wid & 3) * 64;
    const int bx = blockIdx.x;
    const int grid = gridDim.x;

    const int my_nt = (ntiles - 1 - bx) / grid + 1;
    const int my_iters = my_nt * KITER;

    uint32_t sbase = (smem_u32(dynsmem) + 1023u) & ~1023u;

    const int lrow = tid >> 1;
    const int lc4  = (tid & 1) * 4;
    uint32_t soffA[4], soffB1[4];
#pragma unroll
    for (int c = 0; c < 4; ++c) {
        uint32_t offA = (uint32_t)lrow * 128 + (uint32_t)(lc4 + c) * 16;
        soffA[c] = offA ^ ((offA >> 3) & 0x70);
        uint32_t offB1 = (uint32_t)(lrow + 128) * 128 + (uint32_t)(lc4 + c) * 16;
        soffB1[c] = offB1 ^ ((offB1 >> 3) & 0x70);
    }
    const int gcol = lc4 * 8;

    int ld_tile = bx;
    int ld_tm = ld_tile / ntN;
    int ld_tn = ld_tile - ld_tm * ntN;
    int ld_kk = 0;
    int ld_stage = 0;

    auto load_stage = [&]() {
        const __half* gA  = Ah + (size_t)(ld_tm * BM + lrow) * K + ld_kk * BKQ + gcol;
        const __half* gB0 = Bh + (size_t)(ld_tn * BN + lrow) * K + ld_kk * BKQ + gcol;
        const __half* gB1 = gB0 + (size_t)128 * K;
        uint32_t st = sbase + (uint32_t)(ld_stage & (NSTAGE - 1)) * STG;
#pragma unroll
        for (int c = 0; c < 4; ++c) {
            cp16(st + T_A + soffA[c],  gA  + c * 8);
            cp16(st + T_B + soffA[c],  gB0 + c * 8);
            cp16(st + T_B + soffB1[c], gB1 + c * 8);
        }
        CP_COMMIT();
        ++ld_stage;
        if (++ld_kk == KITER) {
            ld_kk = 0;
            ld_tile += grid;
            ld_tm = ld_tile / ntN;
            ld_tn = ld_tile - ld_tm * ntN;
        }
    };

    uint32_t a_rt[4], a_xr[4];
#pragma unroll
    for (int ti = 0; ti < 4; ++ti) {
        int r = wm + ti * 16 + (lane & 15);
        a_rt[ti] = (uint32_t)r * 128;
        a_xr[ti] = (uint32_t)(r & 7) << 4;
    }
    const uint32_t a_cb = (uint32_t)(lane >> 4) * 16;
    uint32_t b_rt[4], b_xr[4];
#pragma unroll
    for (int ni = 0; ni < 4; ++ni) {
        int r = wn + ni * 16 + (lane & 7) + (lane >> 4) * 8;
        b_rt[ni] = (uint32_t)r * 128;
        b_xr[ni] = (uint32_t)(r & 7) << 4;
    }
    const uint32_t b_cb = (uint32_t)((lane >> 3) & 1) * 16;

    float acc[4][8][4];
#pragma unroll
    for (int i = 0; i < 4; ++i)
#pragma unroll
        for (int j = 0; j < 8; ++j)
#pragma unroll
            for (int q = 0; q < 4; ++q) acc[i][j][q] = 0.f;

    load_stage();
    load_stage();

    for (int cp = 0; cp < my_iters; cp += 2) {
        CP_WAIT(0);
        __syncthreads();
        if (cp + 2 < my_iters) load_stage();
        if (cp + 3 < my_iters) load_stage();

        const uint32_t base0 = sbase + (uint32_t)((cp)     & (NSTAGE - 1)) * STG;
        const uint32_t base1 = sbase + (uint32_t)((cp + 1) & (NSTAGE - 1)) * STG;

        uint32_t ah[2][4][4], bh[2][4][4];
#pragma unroll
        for (int ni = 0; ni < 4; ++ni)
            ldsm_x4(bh[0][ni], base0 + T_B + b_rt[ni] + (b_cb ^ b_xr[ni]));
#pragma unroll
        for (int ti = 0; ti < 4; ++ti)
            ldsm_x4(ah[0][ti], base0 + T_A + a_rt[ti] + (a_cb ^ a_xr[ti]));

#pragma unroll
        for (int s = 0; s < 8; ++s) {
            const int cur = s & 1;
            const int nx  = cur ^ 1;
            if (s < 7) {
                const uint32_t bb = (s + 1 < 4) ? base0 : base1;
                const uint32_t kb = (uint32_t)((s + 1) & 3) * 32;
#pragma unroll
                for (int ni = 0; ni < 4; ++ni)
                    ldsm_x4(bh[nx][ni], bb + T_B + b_rt[ni] + ((b_cb + kb) ^ b_xr[ni]));
#pragma unroll
                for (int ti = 0; ti < 4; ++ti)
                    ldsm_x4(ah[nx][ti], bb + T_A + a_rt[ti] + ((a_cb + kb) ^ a_xr[ti]));
            }
#pragma unroll
            for (int mi = 0; mi < 4; ++mi)
#pragma unroll
                for (int ni = 0; ni < 4; ++ni) {
                    MMA_F16(acc[mi][2*ni],   ah[cur][mi], bh[cur][ni][0], bh[cur][ni][1]);
                    MMA_F16(acc[mi][2*ni+1], ah[cur][mi], bh[cur][ni][2], bh[cur][ni][3]);
                }
        }

        if (((cp + 1) & (KITER - 1)) == KITER - 1) {
            int tile = bx + ((cp + 1) >> 4) * grid;
            int tm = tile / ntN;
            int tn = tile - tm * ntN;
#pragma unroll
            for (int mi = 0; mi < 4; ++mi) {
                int gm = tm * BM + wm + mi * 16 + (lane >> 2);
#pragma unroll
                for (int ni = 0; ni < 8; ++ni) {
                    int gn = tn * BN + wn + ni * 8 + (lane & 3) * 2;
                    if constexpr (sizeof(OutT) == 4) {
                        float2 v0 = make_float2(acc[mi][ni][0], acc[mi][ni][1]);
                        float2 v1 = make_float2(acc[mi][ni][2], acc[mi][ni][3]);
                        *(float2*)((float*)C + (size_t)gm * ldc + gn) = v0;
                        *(float2*)((float*)C + (size_t)(gm + 8) * ldc + gn) = v1;
                    } else {
                        __half2 h0; h0.x = __float2half_rn(acc[mi][ni][0]); h0.y = __float2half_rn(acc[mi][ni][1]);
                        __half2 h1; h1.x = __float2half_rn(acc[mi][ni][2]); h1.y = __float2half_rn(acc[mi][ni][3]);
                        *(__half2*)((__half*)C + (size_t)gm * ldc + gn) = h0;
                        *(__half2*)((__half*)C + (size_t)(gm + 8) * ldc + gn) = h1;
                    }
                }
            }
#pragma unroll
            for (int i = 0; i < 4; ++i)
#pragma unroll
                for (int j = 0; j < 8; ++j)
#pragma unroll
                    for (int q = 0; q < 4; ++q) acc[i][j][q] = 0.f;
        }
    }
}

// ---------------- fused RoPE + 16x16 head-attn, 4 tokens/block, fp16 smem ----------------
// smem layout (bytes): qh[64][72] fp16 (9216) | kh (9216) | vh (9216) |
//                      sc[64][17] f32 (4352) | cs[128] f32 (512) | sn[128] f32 (512)
#define PADH 72          // halfs per row (144 B, 9 x uint4)
#define PADU 9           // uint4 per row
#define AQ_B 0
#define AK_B 9216
#define AV_B 18432
#define ASC_B 27648
#define ACS_B 32000
#define ASN_B 32512
#define ATTN_DYN 33024

__global__ __launch_bounds__(256) void attn_kernel()
{
    char* smb = dynsmem;
    __half* qh = (__half*)(smb + AQ_B);
    __half* kh = (__half*)(smb + AK_B);
    __half* vh = (__half*)(smb + AV_B);
    float*  sc = (float*)(smb + ASC_B);
    float*  cs = (float*)(smb + ACS_B);
    float*  sn = (float*)(smb + ASN_B);
    uint4* qu = (uint4*)qh;
    uint4* ku = (uint4*)kh;
    uint4* vu = (uint4*)vh;

    const int tok0 = blockIdx.x * 4;
    const int tid = threadIdx.x;

    if (tid < 128) {
        int tk = tid >> 5, d2 = tid & 31;
        int t = (tok0 + tk) & (TT - 1);
        cs[tk*32 + d2] = g_cos[t*32 + d2];
        sn[tk*32 + d2] = g_sin[t*32 + d2];
    }

    // ---- fill: pure uint4 copy, 6/thread (4 tok x 384 half8-chunks)
    const uint4* base = (const uint4*)(g_qkv + (size_t)tok0 * QKVC);
#pragma unroll
    for (int r = 0; r < 6; ++r) {
        int id = r * 256 + tid;          // 0..1535
        uint4 raw = base[id];
        int tk = id / 384;
        int f  = id - tk * 384;          // 0..383
        int s  = f >> 7;                 // 0=q 1=k 2=v
        int h  = (f >> 3) & 15;
        int g  = f & 7;                  // half8 group within row
        uint4* dst = (s == 0 ? qu : s == 1 ? ku : vu);
        dst[(tk*16 + h) * PADU + g] = raw;
    }
    __syncthreads();

    // ---- RoPE: 4 tok x (q,k) x 16 h x 8 groups = 1024 -> 4/thread
#pragma unroll
    for (int r = 0; r < 4; ++r) {
        int idx = tid + 256 * r;
        int tk = idx >> 8;
        int which = (idx >> 7) & 1;
        int h = (idx >> 3) & 15;
        int g = idx & 7;                 // half8 group: pairs 4g..4g+3
        uint4* p = (which ? ku : qu) + (tk*16 + h) * PADU + g;
        uint4 raw = *p;
        __half2* hp = (__half2*)&raw;
        const float* cb = cs + tk*32 + 4*g;
        const float* sb = sn + tk*32 + 4*g;
#pragma unroll
        for (int j = 0; j < 4; ++j) {
            float2 v = __half22float2(hp[j]);
            float c = cb[j], s = sb[j];
            hp[j] = __floats2half2_rn(v.x*c - v.y*s, v.y*c + v.x*s);
        }
        *p = raw;
    }
    __syncthreads();

    // ---- scores: 4x4 register block, d split across 4 adjacent lanes (16 d each = 2 uint4)
    {
        int tk  = tid >> 6;
        int bi  = (tid >> 2) & 15;
        int dq  = tid & 3;
        int hq0 = (bi >> 2) * 4;
        int hk0 = (bi & 3) * 4;
        const uint4* qb = qu + (tk*16 + hq0) * PADU + dq * 2;
        const uint4* kb = ku + (tk*16 + hk0) * PADU + dq * 2;
        float s[4][4];
#pragma unroll
        for (int i = 0; i < 4; ++i)
#pragma unroll
            for (int j = 0; j < 4; ++j) s[i][j] = 0.f;
#pragma unroll
        for (int it = 0; it < 2; ++it) {
            float2 qa[4][4], ka[4][4];
#pragma unroll
            for (int i = 0; i < 4; ++i) {
                uint4 raw = qb[i * PADU + it];
                const __half2* hp = (const __half2*)&raw;
#pragma unroll
                for (int j = 0; j < 4; ++j) qa[i][j] = __half22float2(hp[j]);
            }
#pragma unroll
            for (int i = 0; i < 4; ++i) {
                uint4 raw = kb[i * PADU + it];
                const __half2* hp = (const __half2*)&raw;
#pragma unroll
                for (int j = 0; j < 4; ++j) ka[i][j] = __half22float2(hp[j]);
            }
#pragma unroll
            for (int i = 0; i < 4; ++i)
#pragma unroll
                for (int j = 0; j < 4; ++j)
#pragma unroll
                    for (int c = 0; c < 4; ++c) {
                        s[i][j] = fmaf(qa[i][c].x, ka[j][c].x, s[i][j]);
                        s[i][j] = fmaf(qa[i][c].y, ka[j][c].y, s[i][j]);
                    }
        }
#pragma unroll
        for (int i = 0; i < 4; ++i)
#pragma unroll
            for (int j = 0; j < 4; ++j) {
                float v = s[i][j];
                v += __shfl_xor_sync(0xffffffffu, v, 1);
                v += __shfl_xor_sync(0xffffffffu, v, 2);
                s[i][j] = v;
            }
        if (dq == 0) {
#pragma unroll
            for (int i = 0; i < 4; ++i)
#pragma unroll
                for (int j = 0; j < 4; ++j)
                    sc[(tk*16 + hq0 + i) * 17 + hk0 + j] = s[i][j] * 0.125f;
        }
    }
    __syncthreads();

    // ---- softmax: 64 rows
    if (tid < 64) {
        float* row = sc + tid * 17;
        float mx = -1e30f;
#pragma unroll
        for (int j = 0; j < 16; ++j) mx = fmaxf(mx, row[j]);
        float sum = 0.f;
#pragma unroll
        for (int j = 0; j < 16; ++j) { float e = expf(row[j] - mx); row[j] = e; sum += e; }
        float inv = 1.f / sum;
#pragma unroll
        for (int j = 0; j < 16; ++j) row[j] *= inv;
    }
    __syncthreads();

    // ---- out: thread = (tk, hq-pair, d8); v uint4 (8 halfs) reused across 2 hq
    {
        int tk  = tid >> 6;
        int rr  = tid & 63;
        int hq0 = (rr >> 3) * 2;         // 0,2,..,14
        int d8  = rr & 7;
        const uint4* vb = vu + (tk*16) * PADU + d8;
        const float* s0 = sc + (tk*16 + hq0) * 17;
        const float* s1 = s0 + 17;
        float o0[8], o1[8];
#pragma unroll
        for (int j = 0; j < 8; ++j) { o0[j] = 0.f; o1[j] = 0.f; }
#pragma unroll
        for (int hk = 0; hk < 16; ++hk) {
            uint4 raw = vb[hk * PADU];
            const __half2* hp = (const __half2*)&raw;
            float w0 = s0[hk], w1 = s1[hk];
#pragma unroll
            for (int j = 0; j < 4; ++j) {
                float2 v = __half22float2(hp[j]);
                o0[2*j]   = fmaf(w0, v.x, o0[2*j]);
                o0[2*j+1] = fmaf(w0, v.y, o0[2*j+1]);
                o1[2*j]   = fmaf(w1, v.x, o1[2*j]);
                o1[2*j+1] = fmaf(w1, v.y, o1[2*j+1]);
            }
        }
        int tg = tok0 + tk;
        int b = tg >> 13, t = tg & (TT - 1);
        size_t obase = ((size_t)b * TT + (t >> 4)) * (size_t)CC + (size_t)(t & 15) * DD + (size_t)d8 * 8;
        uint4 pk0, pk1;
        __half2* p0 = (__half2*)&pk0;
        __half2* p1 = (__half2*)&pk1;
#pragma unroll
        for (int j = 0; j < 4; ++j) {
            p0[j] = __floats2half2_rn(o0[2*j], o0[2*j+1]);
            p1[j] = __floats2half2_rn(o1[2*j], o1[2*j+1]);
        }
        *(uint4*)(g_sh + obase + (size_t)hq0 * 512 * CC)       = pk0;
        *(uint4*)(g_sh + obase + (size_t)(hq0 + 1) * 512 * CC) = pk1;
    }
}

// ---------------------------------------------------------------------------
extern "C" void kernel_launch(void* const* d_in, const int* in_sizes, int n_in,
                              void* d_out, int out_size)
{
    const float* x    = (const float*)d_in[0];
    const float* Wqkv = (const float*)d_in[1];
    const float* Wout = (const float*)d_in[2];
    float* out = (float*)d_out;

    __half *qkv_p, *xh, *sh, *wqh, *woh;
    cudaGetSymbolAddress((void**)&qkv_p, g_qkv);
    cudaGetSymbolAddress((void**)&xh, g_xh);
    cudaGetSymbolAddress((void**)&sh, g_sh);
    cudaGetSymbolAddress((void**)&wqh, g_wqh);
    cudaGetSymbolAddress((void**)&woh, g_woh);

    int nsm = 148;
    cudaDeviceGetAttribute(&nsm, cudaDevAttrMultiProcessorCount, 0);

    cudaFuncSetAttribute(gemm_mma<__half>, cudaFuncAttributeMaxDynamicSharedMemorySize, GEMM_DYN);
    cudaFuncSetAttribute(gemm_mma<float>,  cudaFuncAttributeMaxDynamicSharedMemorySize, GEMM_DYN);
    cudaFuncSetAttribute(attn_kernel,      cudaFuncAttributeMaxDynamicSharedMemorySize, ATTN_DYN);

    rope_table_kernel<<<(TT*32 + 255) / 256, 256>>>();
    cvt_all_kernel<<<5120, 256>>>((const float4*)x, (const float4*)Wqkv, (const float4*)Wout,
                                  (uint2*)xh, (uint2*)wqh, (uint2*)woh);

    // GEMM1: qkv(fp16) = x @ Wqkv^T  (M=16384, N=3072, K=1024)
    {
        int ntiles = (QKVC / BN) * (MTOT / BM);
        int grid = ntiles < nsm ? ntiles : nsm;
        gemm_mma<__half><<<grid, 256, GEMM_DYN>>>(xh, wqh, qkv_p, QKVC, CC, QKVC / BN, ntiles);
    }

    // fused RoPE + head-attention + scramble (fp16 smem, 6 CTAs/SM)
    attn_kernel<<<MTOT / 4, 256, ATTN_DYN>>>();

    // GEMM2: out = scr @ Wout^T (M=16384, N=1024, K=1024)
    {
        int ntiles = (CC / BN) * (MTOT / BM);
        int grid = ntiles < nsm ? ntiles : nsm;
        gemm_mma<float><<<grid, 256, GEMM_DYN>>>(sh, woh, out, CC, CC, CC / BN, ntiles);
    }
}